// round 7
// baseline (speedup 1.0000x reference)
#include <cuda_runtime.h>
#include <cuda_bf16.h>
#include <math.h>
#include <stdint.h>

// ============================================================================
// SDEembedding on GB300 — HMMA bf16 NT pipeline, 3-stage cp.async.
//   prep:  x -> xh/xl ; W -> Wh/Wl ; E -> Eh and E^T -> Eth  (bf16)
//   K1: q = tanh(xh/xl @ (Wh/Wl)^T)   3 combos, tile 128x64  (grid 256)
//   K2: Sb = bf16(exp(qh @ Eh^T)), sums += rowsum, tile 128x128 (grid 2528)
//   K4: out = (Sb @ Eth^T) * (1/sums) + q, tile 128x64 (grid 256, 3 CTA/SM)
// ============================================================================

static constexpr int Mdim = 4096, Ddim = 512, Cdim = 4000, Vdim = 10000;

__device__ __align__(16) __nv_bfloat16 g_xh[(size_t)Mdim * Cdim];
__device__ __align__(16) __nv_bfloat16 g_xl[(size_t)Mdim * Cdim];
__device__ __align__(16) __nv_bfloat16 g_Wh[(size_t)Ddim * Cdim];
__device__ __align__(16) __nv_bfloat16 g_Wl[(size_t)Ddim * Cdim];
__device__ __align__(16) __nv_bfloat16 g_qh[(size_t)Mdim * Ddim];
__device__ __align__(16) __nv_bfloat16 g_Eh[(size_t)Vdim * Ddim];
__device__ __align__(16) __nv_bfloat16 g_Eth[(size_t)Ddim * Vdim];
__device__ __align__(16) __nv_bfloat16 g_Sb[(size_t)Mdim * Vdim];
__device__ float g_sums[Mdim];

#define SA 40   // smem row stride (bf16) = 80 B: conflict-free ldmatrix
static constexpr int APB = 10240;     // A plane bytes: 128 rows * 80 B

__device__ __forceinline__ uint32_t smem_u32(const void* p) {
    uint32_t a;
    asm("{ .reg .u64 t; cvta.to.shared.u64 t, %1; cvt.u32.u64 %0, t; }"
        : "=r"(a) : "l"(p));
    return a;
}
__device__ __forceinline__ void cpa16(uint32_t dst, const void* src, bool pred) {
    int sz = pred ? 16 : 0;
    asm volatile("cp.async.cg.shared.global [%0], [%1], 16, %2;"
                 :: "r"(dst), "l"(src), "r"(sz) : "memory");
}
template <int Ng>
__device__ __forceinline__ void cpa_wait() {
    asm volatile("cp.async.wait_group %0;" :: "n"(Ng) : "memory");
}
__device__ __forceinline__ void cpa_commit() {
    asm volatile("cp.async.commit_group;" ::: "memory");
}
__device__ __forceinline__ void mma_bf16(float* c, const uint32_t* a, const uint32_t* b) {
    asm volatile(
        "mma.sync.aligned.m16n8k16.row.col.f32.bf16.bf16.f32 "
        "{%0,%1,%2,%3},{%4,%5,%6,%7},{%8,%9},{%0,%1,%2,%3};"
        : "+f"(c[0]), "+f"(c[1]), "+f"(c[2]), "+f"(c[3])
        : "r"(a[0]), "r"(a[1]), "r"(a[2]), "r"(a[3]), "r"(b[0]), "r"(b[1]));
}
__device__ __forceinline__ void ldm_x4(uint32_t& r0, uint32_t& r1,
                                       uint32_t& r2, uint32_t& r3, uint32_t addr) {
    asm volatile("ldmatrix.sync.aligned.m8n8.x4.shared.b16 {%0,%1,%2,%3}, [%4];"
                 : "=r"(r0), "=r"(r1), "=r"(r2), "=r"(r3) : "r"(addr));
}
__device__ __forceinline__ uint32_t packbf(float a, float b) {
    return (uint32_t)__bfloat16_as_ushort(__float2bfloat16_rn(a)) |
           ((uint32_t)__bfloat16_as_ushort(__float2bfloat16_rn(b)) << 16);
}
__device__ __forceinline__ void split2(float x, float y, uint32_t& hi, uint32_t& lo) {
    __nv_bfloat16 hx = __float2bfloat16_rn(x);
    __nv_bfloat16 hy = __float2bfloat16_rn(y);
    hi = (uint32_t)__bfloat16_as_ushort(hx) | ((uint32_t)__bfloat16_as_ushort(hy) << 16);
    lo = packbf(x - __bfloat162float(hx), y - __bfloat162float(hy));
}

// ---------------------------------------------------------------------------
// NT GEMM: C[m,n] = sum_k A[m,k]*B[n,k]. CTA 128 x BN x 32, 8 warps (2m x 4n).
// PA/PB: bf16 planes per operand (2 = hi/lo split). Combos: hh (+h*bl)(+al*bh).
// EPI: 1 = tanh -> Cf fp32 + Cbh bf16 ; 2 = *(1/sums[m]) + R -> Cf ;
//      3 = exp -> Cbh bf16, atomicAdd row sums.  3-stage cp.async pipeline.
// ---------------------------------------------------------------------------
template <int EPI, int PA, int PB, int BN, int MINB>
__global__ __launch_bounds__(256, MINB)
void gemm_nt(const __nv_bfloat16* __restrict__ Agh, const __nv_bfloat16* __restrict__ Agl,
             const __nv_bfloat16* __restrict__ Bgh, const __nv_bfloat16* __restrict__ Bgl,
             float* __restrict__ Cf, __nv_bfloat16* __restrict__ Cbh,
             const float* __restrict__ Rres, float* __restrict__ sums,
             int N, int K)
{
    constexpr int BPB    = BN * 80;          // B plane bytes
    constexpr int OFF_AH = 0;
    constexpr int OFF_AL = APB;              // valid iff PA==2
    constexpr int OFF_BH = PA * APB;
    constexpr int OFF_BL = PA * APB + BPB;   // valid iff PB==2
    constexpr int BUF    = PA * APB + PB * BPB;
    constexpr int NLD    = BN / 64;          // B x4-ldmatrix loads per plane
    constexpr int NFR    = BN / 32;          // n-fragments per warp

    extern __shared__ char smem[];
    const uint32_t sb = smem_u32(smem);

    const int tid  = threadIdx.x;
    const int wid  = tid >> 5;
    const int lane = tid & 31;
    const int g    = lane >> 2;
    const int tig  = lane & 3;
    const int wm   = wid & 1;
    const int wn   = wid >> 1;
    const int bm0  = blockIdx.y * 128;
    const int bn0  = blockIdx.x * BN;

    const int lrow = lane & 7;
    const int lb3  = (lane >> 3) & 1;
    const int lb4  = lane >> 4;
    const uint32_t a_lane = (uint32_t)(((wm * 64 + lb3 * 8 + lrow) * SA + lb4 * 8) * 2);
    const uint32_t b_lane = (uint32_t)(((wn * (BN / 4) + lb4 * 8 + lrow) * SA + lb3 * 8) * 2);

    float acc[4][NFR][4];
#pragma unroll
    for (int mi = 0; mi < 4; mi++)
#pragma unroll
        for (int ni = 0; ni < NFR; ni++)
#pragma unroll
            for (int j = 0; j < 4; j++) acc[mi][ni][j] = 0.f;

    const int NC = (K + 31) >> 5;

    auto load_chunk = [&](int stage, int kt) {
        const uint32_t sbuf = sb + (uint32_t)(stage * BUF);
#pragma unroll
        for (int i = 0; i < 2; i++) {          // A: 128 rows x 4 groups
            const int e   = tid + i * 256;
            const int row = e >> 2;
            const int kc  = (e & 3) << 3;
            const int gk  = kt + kc;
            const bool kok = gk < K;
            const uint32_t d = (uint32_t)(row * (SA * 2) + kc * 2);
            const size_t aoff = (size_t)(bm0 + row) * K + gk;
            cpa16(sbuf + OFF_AH + d, Agh + aoff, kok);
            if (PA == 2) cpa16(sbuf + OFF_AL + d, Agl + aoff, kok);
        }
#pragma unroll
        for (int i = 0; i < BN / 64; i++) {    // B: BN rows x 4 groups
            const int e   = tid + i * 256;
            const int row = e >> 2;
            const int kc  = (e & 3) << 3;
            const int gk  = kt + kc;
            const bool nok = ((bn0 + row) < N) && (gk < K);
            const uint32_t d = (uint32_t)(row * (SA * 2) + kc * 2);
            const size_t boff = (size_t)(bn0 + row) * K + gk;
            cpa16(sbuf + OFF_BH + d, Bgh + boff, nok);
            if (PB == 2) cpa16(sbuf + OFF_BL + d, Bgl + boff, nok);
        }
        cpa_commit();
    };

    load_chunk(0, 0);
    load_chunk(1, 32);

    int stage = 0;
    for (int c = 0; c < NC; c++) {
        if (c + 1 < NC) cpa_wait<1>(); else cpa_wait<0>();
        __syncthreads();

        if (c + 2 < NC) {
            int ns = stage + 2; if (ns >= 3) ns -= 3;
            load_chunk(ns, (c + 2) << 5);
        }

        const uint32_t bufb = sb + (uint32_t)(stage * BUF);
#pragma unroll
        for (int ks = 0; ks < 2; ks++) {
            const uint32_t ko = (uint32_t)(ks * 32);
            uint32_t ah[4][4], al[4][4], bh[NFR][2], bl[NFR][2];
#pragma unroll
            for (int mi = 0; mi < 4; mi++)
                ldm_x4(ah[mi][0], ah[mi][1], ah[mi][2], ah[mi][3],
                       bufb + OFF_AH + a_lane + (uint32_t)(mi * 16 * SA * 2) + ko);
            if (PA == 2) {
#pragma unroll
                for (int mi = 0; mi < 4; mi++)
                    ldm_x4(al[mi][0], al[mi][1], al[mi][2], al[mi][3],
                           bufb + OFF_AL + a_lane + (uint32_t)(mi * 16 * SA * 2) + ko);
            }
#pragma unroll
            for (int pp = 0; pp < NLD; pp++)
                ldm_x4(bh[2 * pp][0], bh[2 * pp][1], bh[2 * pp + 1][0], bh[2 * pp + 1][1],
                       bufb + OFF_BH + b_lane + (uint32_t)(pp * 16 * SA * 2) + ko);
            if (PB == 2) {
#pragma unroll
                for (int pp = 0; pp < NLD; pp++)
                    ldm_x4(bl[2 * pp][0], bl[2 * pp][1], bl[2 * pp + 1][0], bl[2 * pp + 1][1],
                           bufb + OFF_BL + b_lane + (uint32_t)(pp * 16 * SA * 2) + ko);
            }

#pragma unroll
            for (int mi = 0; mi < 4; mi++)
#pragma unroll
                for (int ni = 0; ni < NFR; ni++)
                    mma_bf16(acc[mi][ni], ah[mi], bh[ni]);
            if (PB == 2) {
#pragma unroll
                for (int mi = 0; mi < 4; mi++)
#pragma unroll
                    for (int ni = 0; ni < NFR; ni++)
                        mma_bf16(acc[mi][ni], ah[mi], bl[ni]);
            }
            if (PA == 2) {
#pragma unroll
                for (int mi = 0; mi < 4; mi++)
#pragma unroll
                    for (int ni = 0; ni < NFR; ni++)
                        mma_bf16(acc[mi][ni], al[mi], bh[ni]);
            }
        }
        if (++stage == 3) stage = 0;
    }

    // ---- epilogue ----
#pragma unroll
    for (int mi = 0; mi < 4; mi++) {
        const int gm = bm0 + wm * 64 + mi * 16 + g;
        float s0 = 1.f, s1 = 1.f;
        if (EPI == 2) { s0 = 1.0f / sums[gm]; s1 = 1.0f / sums[gm + 8]; }
        float rs01 = 0.f, rs23 = 0.f;
#pragma unroll
        for (int ni = 0; ni < NFR; ni++) {
            const int gn = bn0 + wn * (BN / 4) + ni * 8 + tig * 2;
            float* cc = acc[mi][ni];
            if (EPI == 3) {
                if (gn < N) {
                    const float e0 = __expf(cc[0]), e1 = __expf(cc[1]);
                    const float e2 = __expf(cc[2]), e3 = __expf(cc[3]);
                    rs01 += e0 + e1;
                    rs23 += e2 + e3;
                    *(uint32_t*)(Cbh + (size_t)gm * N + gn)       = packbf(e0, e1);
                    *(uint32_t*)(Cbh + (size_t)(gm + 8) * N + gn) = packbf(e2, e3);
                }
            } else if (gn < N) {
                float2 v0 = make_float2(cc[0], cc[1]);
                float2 v1 = make_float2(cc[2], cc[3]);
                if (EPI == 1) {
                    v0.x = tanhf(v0.x); v0.y = tanhf(v0.y);
                    v1.x = tanhf(v1.x); v1.y = tanhf(v1.y);
                    *(uint32_t*)(Cbh + (size_t)gm * N + gn)       = packbf(v0.x, v0.y);
                    *(uint32_t*)(Cbh + (size_t)(gm + 8) * N + gn) = packbf(v1.x, v1.y);
                }
                if (EPI == 2) {
                    const float2 r0 = *(const float2*)(Rres + (size_t)gm * N + gn);
                    const float2 r1 = *(const float2*)(Rres + (size_t)(gm + 8) * N + gn);
                    v0.x = v0.x * s0 + r0.x; v0.y = v0.y * s0 + r0.y;
                    v1.x = v1.x * s1 + r1.x; v1.y = v1.y * s1 + r1.y;
                }
                *(float2*)(Cf + (size_t)gm * N + gn)       = v0;
                *(float2*)(Cf + (size_t)(gm + 8) * N + gn) = v1;
            }
        }
        if (EPI == 3) {
            rs01 += __shfl_xor_sync(0xffffffffu, rs01, 1);
            rs01 += __shfl_xor_sync(0xffffffffu, rs01, 2);
            rs23 += __shfl_xor_sync(0xffffffffu, rs23, 1);
            rs23 += __shfl_xor_sync(0xffffffffu, rs23, 2);
            if (tig == 0) {
                atomicAdd(&sums[gm],     rs01);
                atomicAdd(&sums[gm + 8], rs23);
            }
        }
    }
}

// ---------------------------------------------------------------------------
__global__ __launch_bounds__(256)
void split_f32(const float* __restrict__ in, __nv_bfloat16* __restrict__ h,
               __nv_bfloat16* __restrict__ l, int n4)
{
    const int i = blockIdx.x * 256 + threadIdx.x;
    if (i < n4) {
        const float4 v = *(const float4*)(in + 4 * (size_t)i);
        uint32_t h0, l0, h1, l1;
        split2(v.x, v.y, h0, l0);
        split2(v.z, v.w, h1, l1);
        *(uint2*)(h + 4 * (size_t)i) = make_uint2(h0, h1);
        *(uint2*)(l + 4 * (size_t)i) = make_uint2(l0, l1);
    }
}

// E prep: Eh = bf16(E) [V,D]; Eth = bf16(E^T) [D,V]. Block (32,8).
__global__ __launch_bounds__(256)
void prep_E(const float* __restrict__ E,
            __nv_bfloat16* __restrict__ Eh, __nv_bfloat16* __restrict__ Eth,
            int V, int D)
{
    __shared__ float tile[32][33];
    const int d0 = blockIdx.x * 32;
    const int v0 = blockIdx.y * 32;
    const int tx = threadIdx.x, ty = threadIdx.y;

#pragma unroll
    for (int j = 0; j < 4; j++) {
        const int v = v0 + ty + 8 * j;
        const int d = d0 + tx;
        float val = 0.f;
        if (v < V) val = E[(size_t)v * D + d];
        tile[ty + 8 * j][tx] = val;
        if (v < V) Eh[(size_t)v * D + d] = __float2bfloat16_rn(val);
    }
    __syncthreads();
#pragma unroll
    for (int j = 0; j < 4; j++) {
        const int d = d0 + ty + 8 * j;
        const int v = v0 + tx;
        if (v < V)
            Eth[(size_t)d * V + v] = __float2bfloat16_rn(tile[tx][ty + 8 * j]);
    }
}

// ---------------------------------------------------------------------------
extern "C" void kernel_launch(void* const* d_in, const int* in_sizes, int n_in,
                              void* d_out, int out_size)
{
    (void)in_sizes; (void)n_in; (void)out_size;
    const float* x  = (const float*)d_in[0];   // [4096, 4000]
    const float* Wp = (const float*)d_in[1];   // [512, 4000]
    const float* E  = (const float*)d_in[2];   // [10000, 512]
    float* out = (float*)d_out;                // [4096, 512]

    __nv_bfloat16 *xh, *xl, *Wh, *Wl, *qh, *Eh, *Eth, *Sb;
    float* sums;
    cudaGetSymbolAddress((void**)&xh,  g_xh);
    cudaGetSymbolAddress((void**)&xl,  g_xl);
    cudaGetSymbolAddress((void**)&Wh,  g_Wh);
    cudaGetSymbolAddress((void**)&Wl,  g_Wl);
    cudaGetSymbolAddress((void**)&qh,  g_qh);
    cudaGetSymbolAddress((void**)&Eh,  g_Eh);
    cudaGetSymbolAddress((void**)&Eth, g_Eth);
    cudaGetSymbolAddress((void**)&Sb,  g_Sb);
    cudaGetSymbolAddress((void**)&sums, g_sums);

    // K1: PA=2 PB=2 BN=64  -> stage = 2*10240 + 2*5120  = 30720; 3 st = 92160
    // K2: PA=1 PB=1 BN=128 -> stage = 10240 + 10240     = 20480; 3 st = 61440
    // K4: PA=1 PB=1 BN=64  -> stage = 10240 + 5120      = 15360; 3 st = 46080
    constexpr int SM_K1 = 3 * 30720;
    constexpr int SM_K2 = 3 * 20480;
    constexpr int SM_K4 = 3 * 15360;
    cudaFuncSetAttribute((const void*)gemm_nt<1, 2, 2, 64, 2>,
                         cudaFuncAttributeMaxDynamicSharedMemorySize, SM_K1);
    cudaFuncSetAttribute((const void*)gemm_nt<3, 1, 1, 128, 2>,
                         cudaFuncAttributeMaxDynamicSharedMemorySize, SM_K2);
    cudaFuncSetAttribute((const void*)gemm_nt<2, 1, 1, 64, 3>,
                         cudaFuncAttributeMaxDynamicSharedMemorySize, SM_K4);

    cudaMemsetAsync(sums, 0, Mdim * sizeof(float));

    // prep
    split_f32<<<(Mdim * Cdim / 4 + 255) / 256, 256>>>(x, xh, xl, Mdim * Cdim / 4);
    split_f32<<<(Ddim * Cdim / 4 + 255) / 256, 256>>>(Wp, Wh, Wl, Ddim * Cdim / 4);
    prep_E<<<dim3(Ddim / 32, (Vdim + 31) / 32), dim3(32, 8)>>>(E, Eh, Eth, Vdim, Ddim);

    // K1: q = tanh(x @ W^T)   [N=512, K=4000], 3 combos, tile 128x64
    gemm_nt<1, 2, 2, 64, 2><<<dim3(Ddim / 64, Mdim / 128), 256, SM_K1>>>(
        xh, xl, Wh, Wl, out, qh, nullptr, nullptr, Ddim, Cdim);

    // K2: Sb = bf16(exp(qh @ Eh^T)), sums = rowsum   [N=10000, K=512]
    gemm_nt<3, 1, 1, 128, 2><<<dim3((Vdim + 127) / 128, Mdim / 128), 256, SM_K2>>>(
        qh, nullptr, Eh, nullptr, nullptr, Sb, nullptr, sums, Vdim, Ddim);

    // K4: out = (Sb @ Eth^T) / sums + q   [N=512, K=10000], tile 128x64
    gemm_nt<2, 1, 1, 64, 3><<<dim3(Ddim / 64, Mdim / 128), 256, SM_K4>>>(
        Sb, nullptr, Eth, nullptr, out, nullptr, out, sums, Ddim, Vdim);
}

// round 8
// speedup vs baseline: 1.0283x; 1.0283x over previous
#include <cuda_runtime.h>
#include <cuda_bf16.h>
#include <math.h>
#include <stdint.h>

// ============================================================================
// SDEembedding on GB300 — HMMA bf16 NT pipeline, 3-stage cp.async.
//   prep:  x -> xh/xl ; W -> Wh/Wl ; E -> Eh and E^T -> Eth  (bf16)
//   K1: q = tanh(xh/xl @ (Wh/Wl)^T)   3 combos, tile 64x128 (grid 256, 2/SM)
//   K2: Sb = bf16(exp(qh @ Eh^T)), sums += rowsum, tile 128x128 (grid 2528)
//   K4: out = (Sb @ Eth^T) * (1/sums) + q, tile 64x128 (grid 256, 3/SM)
// M-split (not N-split): keeps MMA:LDSM ratio, B planes are L2-resident.
// ============================================================================

static constexpr int Mdim = 4096, Ddim = 512, Cdim = 4000, Vdim = 10000;

__device__ __align__(16) __nv_bfloat16 g_xh[(size_t)Mdim * Cdim];
__device__ __align__(16) __nv_bfloat16 g_xl[(size_t)Mdim * Cdim];
__device__ __align__(16) __nv_bfloat16 g_Wh[(size_t)Ddim * Cdim];
__device__ __align__(16) __nv_bfloat16 g_Wl[(size_t)Ddim * Cdim];
__device__ __align__(16) __nv_bfloat16 g_qh[(size_t)Mdim * Ddim];
__device__ __align__(16) __nv_bfloat16 g_Eh[(size_t)Vdim * Ddim];
__device__ __align__(16) __nv_bfloat16 g_Eth[(size_t)Ddim * Vdim];
__device__ __align__(16) __nv_bfloat16 g_Sb[(size_t)Mdim * Vdim];
__device__ float g_sums[Mdim];

#define SA 40   // smem row stride (bf16) = 80 B: conflict-free ldmatrix

__device__ __forceinline__ uint32_t smem_u32(const void* p) {
    uint32_t a;
    asm("{ .reg .u64 t; cvta.to.shared.u64 t, %1; cvt.u32.u64 %0, t; }"
        : "=r"(a) : "l"(p));
    return a;
}
__device__ __forceinline__ void cpa16(uint32_t dst, const void* src, bool pred) {
    int sz = pred ? 16 : 0;
    asm volatile("cp.async.cg.shared.global [%0], [%1], 16, %2;"
                 :: "r"(dst), "l"(src), "r"(sz) : "memory");
}
template <int Ng>
__device__ __forceinline__ void cpa_wait() {
    asm volatile("cp.async.wait_group %0;" :: "n"(Ng) : "memory");
}
__device__ __forceinline__ void cpa_commit() {
    asm volatile("cp.async.commit_group;" ::: "memory");
}
__device__ __forceinline__ void mma_bf16(float* c, const uint32_t* a, const uint32_t* b) {
    asm volatile(
        "mma.sync.aligned.m16n8k16.row.col.f32.bf16.bf16.f32 "
        "{%0,%1,%2,%3},{%4,%5,%6,%7},{%8,%9},{%0,%1,%2,%3};"
        : "+f"(c[0]), "+f"(c[1]), "+f"(c[2]), "+f"(c[3])
        : "r"(a[0]), "r"(a[1]), "r"(a[2]), "r"(a[3]), "r"(b[0]), "r"(b[1]));
}
__device__ __forceinline__ void ldm_x4(uint32_t& r0, uint32_t& r1,
                                       uint32_t& r2, uint32_t& r3, uint32_t addr) {
    asm volatile("ldmatrix.sync.aligned.m8n8.x4.shared.b16 {%0,%1,%2,%3}, [%4];"
                 : "=r"(r0), "=r"(r1), "=r"(r2), "=r"(r3) : "r"(addr));
}
__device__ __forceinline__ uint32_t packbf(float a, float b) {
    return (uint32_t)__bfloat16_as_ushort(__float2bfloat16_rn(a)) |
           ((uint32_t)__bfloat16_as_ushort(__float2bfloat16_rn(b)) << 16);
}
__device__ __forceinline__ void split2(float x, float y, uint32_t& hi, uint32_t& lo) {
    __nv_bfloat16 hx = __float2bfloat16_rn(x);
    __nv_bfloat16 hy = __float2bfloat16_rn(y);
    hi = (uint32_t)__bfloat16_as_ushort(hx) | ((uint32_t)__bfloat16_as_ushort(hy) << 16);
    lo = packbf(x - __bfloat162float(hx), y - __bfloat162float(hy));
}

// ---------------------------------------------------------------------------
// NT GEMM: C[m,n] = sum_k A[m,k]*B[n,k]. CTA BM x 128 x 32, 8 warps (2m x 4n),
// warp tile (BM/2) x 32.  PA/PB: bf16 planes per operand (2 = hi/lo split).
// Combos: hh (+h*bl if PB==2) (+al*bh if PA==2).
// EPI: 1 = tanh -> Cf fp32 + Cbh bf16 ; 2 = *(1/sums[m]) + R -> Cf ;
//      3 = exp -> Cbh bf16, atomicAdd row sums.  3-stage cp.async pipeline.
// ---------------------------------------------------------------------------
template <int EPI, int PA, int PB, int BM, int MINB>
__global__ __launch_bounds__(256, MINB)
void gemm_nt(const __nv_bfloat16* __restrict__ Agh, const __nv_bfloat16* __restrict__ Agl,
             const __nv_bfloat16* __restrict__ Bgh, const __nv_bfloat16* __restrict__ Bgl,
             float* __restrict__ Cf, __nv_bfloat16* __restrict__ Cbh,
             const float* __restrict__ Rres, float* __restrict__ sums,
             int N, int K)
{
    constexpr int APB    = BM * 80;          // A plane bytes
    constexpr int BPB    = 128 * 80;         // B plane bytes
    constexpr int OFF_AH = 0;
    constexpr int OFF_AL = APB;              // valid iff PA==2
    constexpr int OFF_BH = PA * APB;
    constexpr int OFF_BL = PA * APB + BPB;   // valid iff PB==2
    constexpr int BUF    = PA * APB + PB * BPB;
    constexpr int MI     = BM / 32;          // m-fragments (16 rows) per warp

    extern __shared__ char smem[];
    const uint32_t sb = smem_u32(smem);

    const int tid  = threadIdx.x;
    const int wid  = tid >> 5;
    const int lane = tid & 31;
    const int g    = lane >> 2;
    const int tig  = lane & 3;
    const int wm   = wid & 1;
    const int wn   = wid >> 1;
    const int bm0  = blockIdx.y * BM;
    const int bn0  = blockIdx.x * 128;

    const int lrow = lane & 7;
    const int lb3  = (lane >> 3) & 1;
    const int lb4  = lane >> 4;
    const uint32_t a_lane = (uint32_t)(((wm * (BM / 2) + lb3 * 8 + lrow) * SA + lb4 * 8) * 2);
    const uint32_t b_lane = (uint32_t)(((wn * 32 + lb4 * 8 + lrow) * SA + lb3 * 8) * 2);

    float acc[MI][4][4];
#pragma unroll
    for (int mi = 0; mi < MI; mi++)
#pragma unroll
        for (int ni = 0; ni < 4; ni++)
#pragma unroll
            for (int j = 0; j < 4; j++) acc[mi][ni][j] = 0.f;

    const int NC = (K + 31) >> 5;

    auto load_chunk = [&](int stage, int kt) {
        const uint32_t sbuf = sb + (uint32_t)(stage * BUF);
#pragma unroll
        for (int i = 0; i < BM / 64; i++) {    // A: BM rows x 4 k-groups
            const int e   = tid + i * 256;
            const int row = e >> 2;
            const int kc  = (e & 3) << 3;
            const int gk  = kt + kc;
            const bool kok = gk < K;
            const uint32_t d = (uint32_t)(row * (SA * 2) + kc * 2);
            const size_t aoff = (size_t)(bm0 + row) * K + gk;
            cpa16(sbuf + OFF_AH + d, Agh + aoff, kok);
            if (PA == 2) cpa16(sbuf + OFF_AL + d, Agl + aoff, kok);
        }
#pragma unroll
        for (int i = 0; i < 2; i++) {          // B: 128 rows x 4 k-groups
            const int e   = tid + i * 256;
            const int row = e >> 2;
            const int kc  = (e & 3) << 3;
            const int gk  = kt + kc;
            const bool nok = ((bn0 + row) < N) && (gk < K);
            const uint32_t d = (uint32_t)(row * (SA * 2) + kc * 2);
            const size_t boff = (size_t)(bn0 + row) * K + gk;
            cpa16(sbuf + OFF_BH + d, Bgh + boff, nok);
            if (PB == 2) cpa16(sbuf + OFF_BL + d, Bgl + boff, nok);
        }
        cpa_commit();
    };

    load_chunk(0, 0);
    load_chunk(1, 32);

    int stage = 0;
    for (int c = 0; c < NC; c++) {
        if (c + 1 < NC) cpa_wait<1>(); else cpa_wait<0>();
        __syncthreads();

        if (c + 2 < NC) {
            int ns = stage + 2; if (ns >= 3) ns -= 3;
            load_chunk(ns, (c + 2) << 5);
        }

        const uint32_t bufb = sb + (uint32_t)(stage * BUF);
#pragma unroll
        for (int ks = 0; ks < 2; ks++) {
            const uint32_t ko = (uint32_t)(ks * 32);
            uint32_t ah[MI][4], al[MI][4], bh[4][2], bl[4][2];
#pragma unroll
            for (int mi = 0; mi < MI; mi++)
                ldm_x4(ah[mi][0], ah[mi][1], ah[mi][2], ah[mi][3],
                       bufb + OFF_AH + a_lane + (uint32_t)(mi * 16 * SA * 2) + ko);
            if (PA == 2) {
#pragma unroll
                for (int mi = 0; mi < MI; mi++)
                    ldm_x4(al[mi][0], al[mi][1], al[mi][2], al[mi][3],
                           bufb + OFF_AL + a_lane + (uint32_t)(mi * 16 * SA * 2) + ko);
            }
#pragma unroll
            for (int pp = 0; pp < 2; pp++)
                ldm_x4(bh[2 * pp][0], bh[2 * pp][1], bh[2 * pp + 1][0], bh[2 * pp + 1][1],
                       bufb + OFF_BH + b_lane + (uint32_t)(pp * 16 * SA * 2) + ko);
            if (PB == 2) {
#pragma unroll
                for (int pp = 0; pp < 2; pp++)
                    ldm_x4(bl[2 * pp][0], bl[2 * pp][1], bl[2 * pp + 1][0], bl[2 * pp + 1][1],
                           bufb + OFF_BL + b_lane + (uint32_t)(pp * 16 * SA * 2) + ko);
            }

#pragma unroll
            for (int mi = 0; mi < MI; mi++)
#pragma unroll
                for (int ni = 0; ni < 4; ni++)
                    mma_bf16(acc[mi][ni], ah[mi], bh[ni]);
            if (PB == 2) {
#pragma unroll
                for (int mi = 0; mi < MI; mi++)
#pragma unroll
                    for (int ni = 0; ni < 4; ni++)
                        mma_bf16(acc[mi][ni], ah[mi], bl[ni]);
            }
            if (PA == 2) {
#pragma unroll
                for (int mi = 0; mi < MI; mi++)
#pragma unroll
                    for (int ni = 0; ni < 4; ni++)
                        mma_bf16(acc[mi][ni], al[mi], bh[ni]);
            }
        }
        if (++stage == 3) stage = 0;
    }

    // ---- epilogue ----
#pragma unroll
    for (int mi = 0; mi < MI; mi++) {
        const int gm = bm0 + wm * (BM / 2) + mi * 16 + g;
        float s0 = 1.f, s1 = 1.f;
        if (EPI == 2) { s0 = 1.0f / sums[gm]; s1 = 1.0f / sums[gm + 8]; }
        float rs01 = 0.f, rs23 = 0.f;
#pragma unroll
        for (int ni = 0; ni < 4; ni++) {
            const int gn = bn0 + wn * 32 + ni * 8 + tig * 2;
            float* cc = acc[mi][ni];
            if (EPI == 3) {
                if (gn < N) {
                    const float e0 = __expf(cc[0]), e1 = __expf(cc[1]);
                    const float e2 = __expf(cc[2]), e3 = __expf(cc[3]);
                    rs01 += e0 + e1;
                    rs23 += e2 + e3;
                    *(uint32_t*)(Cbh + (size_t)gm * N + gn)       = packbf(e0, e1);
                    *(uint32_t*)(Cbh + (size_t)(gm + 8) * N + gn) = packbf(e2, e3);
                }
            } else if (gn < N) {
                float2 v0 = make_float2(cc[0], cc[1]);
                float2 v1 = make_float2(cc[2], cc[3]);
                if (EPI == 1) {
                    v0.x = tanhf(v0.x); v0.y = tanhf(v0.y);
                    v1.x = tanhf(v1.x); v1.y = tanhf(v1.y);
                    *(uint32_t*)(Cbh + (size_t)gm * N + gn)       = packbf(v0.x, v0.y);
                    *(uint32_t*)(Cbh + (size_t)(gm + 8) * N + gn) = packbf(v1.x, v1.y);
                }
                if (EPI == 2) {
                    const float2 r0 = *(const float2*)(Rres + (size_t)gm * N + gn);
                    const float2 r1 = *(const float2*)(Rres + (size_t)(gm + 8) * N + gn);
                    v0.x = v0.x * s0 + r0.x; v0.y = v0.y * s0 + r0.y;
                    v1.x = v1.x * s1 + r1.x; v1.y = v1.y * s1 + r1.y;
                }
                *(float2*)(Cf + (size_t)gm * N + gn)       = v0;
                *(float2*)(Cf + (size_t)(gm + 8) * N + gn) = v1;
            }
        }
        if (EPI == 3) {
            rs01 += __shfl_xor_sync(0xffffffffu, rs01, 1);
            rs01 += __shfl_xor_sync(0xffffffffu, rs01, 2);
            rs23 += __shfl_xor_sync(0xffffffffu, rs23, 1);
            rs23 += __shfl_xor_sync(0xffffffffu, rs23, 2);
            if (tig == 0) {
                atomicAdd(&sums[gm],     rs01);
                atomicAdd(&sums[gm + 8], rs23);
            }
        }
    }
}

// ---------------------------------------------------------------------------
__global__ __launch_bounds__(256)
void split_f32(const float* __restrict__ in, __nv_bfloat16* __restrict__ h,
               __nv_bfloat16* __restrict__ l, int n4)
{
    const int i = blockIdx.x * 256 + threadIdx.x;
    if (i < n4) {
        const float4 v = *(const float4*)(in + 4 * (size_t)i);
        uint32_t h0, l0, h1, l1;
        split2(v.x, v.y, h0, l0);
        split2(v.z, v.w, h1, l1);
        *(uint2*)(h + 4 * (size_t)i) = make_uint2(h0, h1);
        *(uint2*)(l + 4 * (size_t)i) = make_uint2(l0, l1);
    }
}

// E prep: Eh = bf16(E) [V,D]; Eth = bf16(E^T) [D,V]. Block (32,8).
__global__ __launch_bounds__(256)
void prep_E(const float* __restrict__ E,
            __nv_bfloat16* __restrict__ Eh, __nv_bfloat16* __restrict__ Eth,
            int V, int D)
{
    __shared__ float tile[32][33];
    const int d0 = blockIdx.x * 32;
    const int v0 = blockIdx.y * 32;
    const int tx = threadIdx.x, ty = threadIdx.y;

#pragma unroll
    for (int j = 0; j < 4; j++) {
        const int v = v0 + ty + 8 * j;
        const int d = d0 + tx;
        float val = 0.f;
        if (v < V) val = E[(size_t)v * D + d];
        tile[ty + 8 * j][tx] = val;
        if (v < V) Eh[(size_t)v * D + d] = __float2bfloat16_rn(val);
    }
    __syncthreads();
#pragma unroll
    for (int j = 0; j < 4; j++) {
        const int d = d0 + ty + 8 * j;
        const int v = v0 + tx;
        if (v < V)
            Eth[(size_t)d * V + v] = __float2bfloat16_rn(tile[tx][ty + 8 * j]);
    }
}

// ---------------------------------------------------------------------------
extern "C" void kernel_launch(void* const* d_in, const int* in_sizes, int n_in,
                              void* d_out, int out_size)
{
    (void)in_sizes; (void)n_in; (void)out_size;
    const float* x  = (const float*)d_in[0];   // [4096, 4000]
    const float* Wp = (const float*)d_in[1];   // [512, 4000]
    const float* E  = (const float*)d_in[2];   // [10000, 512]
    float* out = (float*)d_out;                // [4096, 512]

    __nv_bfloat16 *xh, *xl, *Wh, *Wl, *qh, *Eh, *Eth, *Sb;
    float* sums;
    cudaGetSymbolAddress((void**)&xh,  g_xh);
    cudaGetSymbolAddress((void**)&xl,  g_xl);
    cudaGetSymbolAddress((void**)&Wh,  g_Wh);
    cudaGetSymbolAddress((void**)&Wl,  g_Wl);
    cudaGetSymbolAddress((void**)&qh,  g_qh);
    cudaGetSymbolAddress((void**)&Eh,  g_Eh);
    cudaGetSymbolAddress((void**)&Eth, g_Eth);
    cudaGetSymbolAddress((void**)&Sb,  g_Sb);
    cudaGetSymbolAddress((void**)&sums, g_sums);

    // K1: BM=64  PA=2 PB=2 -> stage = 2*5120 + 2*10240 = 30720; x3 = 92160 (2/SM)
    // K2: BM=128 PA=1 PB=1 -> stage = 10240 + 10240    = 20480; x3 = 61440 (2/SM)
    // K4: BM=64  PA=1 PB=1 -> stage = 5120 + 10240     = 15360; x3 = 46080 (3/SM)
    constexpr int SM_K1 = 3 * 30720;
    constexpr int SM_K2 = 3 * 20480;
    constexpr int SM_K4 = 3 * 15360;
    cudaFuncSetAttribute((const void*)gemm_nt<1, 2, 2, 64, 2>,
                         cudaFuncAttributeMaxDynamicSharedMemorySize, SM_K1);
    cudaFuncSetAttribute((const void*)gemm_nt<3, 1, 1, 128, 2>,
                         cudaFuncAttributeMaxDynamicSharedMemorySize, SM_K2);
    cudaFuncSetAttribute((const void*)gemm_nt<2, 1, 1, 64, 3>,
                         cudaFuncAttributeMaxDynamicSharedMemorySize, SM_K4);

    cudaMemsetAsync(sums, 0, Mdim * sizeof(float));

    // prep
    split_f32<<<(Mdim * Cdim / 4 + 255) / 256, 256>>>(x, xh, xl, Mdim * Cdim / 4);
    split_f32<<<(Ddim * Cdim / 4 + 255) / 256, 256>>>(Wp, Wh, Wl, Ddim * Cdim / 4);
    prep_E<<<dim3(Ddim / 32, (Vdim + 31) / 32), dim3(32, 8)>>>(E, Eh, Eth, Vdim, Ddim);

    // K1: q = tanh(x @ W^T)   [N=512, K=4000], 3 combos, tile 64x128
    gemm_nt<1, 2, 2, 64, 2><<<dim3(Ddim / 128, Mdim / 64), 256, SM_K1>>>(
        xh, xl, Wh, Wl, out, qh, nullptr, nullptr, Ddim, Cdim);

    // K2: Sb = bf16(exp(qh @ Eh^T)), sums = rowsum   [N=10000, K=512]
    gemm_nt<3, 1, 1, 128, 2><<<dim3((Vdim + 127) / 128, Mdim / 128), 256, SM_K2>>>(
        qh, nullptr, Eh, nullptr, nullptr, Sb, nullptr, sums, Vdim, Ddim);

    // K4: out = (Sb @ Eth^T) / sums + q   [N=512, K=10000], tile 64x128
    gemm_nt<2, 1, 1, 64, 3><<<dim3(Ddim / 128, Mdim / 64), 256, SM_K4>>>(
        Sb, nullptr, Eth, nullptr, out, nullptr, out, sums, Ddim, Vdim);
}

// round 9
// speedup vs baseline: 1.0570x; 1.0279x over previous
#include <cuda_runtime.h>
#include <cuda_bf16.h>
#include <math.h>
#include <stdint.h>

// ============================================================================
// SDEembedding on GB300 — HMMA bf16 NT pipeline, 3-stage cp.async,
// warp-pair k-step staggering (SMSP-mates run LDSM/MMA phases out of phase).
//   prep:  x -> xh/xl ; W -> Wh/Wl ; E -> Eh and E^T -> Eth  (bf16)
//   K1: q = tanh(xh/xl @ (Wh/Wl)^T)   3 combos, tile 128x128
//   K2: Sb = bf16(exp(qh @ Eh^T)), sums += rowsum, tile 128x128
//   K4: out = (Sb @ Eth^T) * (1/sums) + q, tile 128x128
// ============================================================================

static constexpr int Mdim = 4096, Ddim = 512, Cdim = 4000, Vdim = 10000;

__device__ __align__(16) __nv_bfloat16 g_xh[(size_t)Mdim * Cdim];
__device__ __align__(16) __nv_bfloat16 g_xl[(size_t)Mdim * Cdim];
__device__ __align__(16) __nv_bfloat16 g_Wh[(size_t)Ddim * Cdim];
__device__ __align__(16) __nv_bfloat16 g_Wl[(size_t)Ddim * Cdim];
__device__ __align__(16) __nv_bfloat16 g_qh[(size_t)Mdim * Ddim];
__device__ __align__(16) __nv_bfloat16 g_Eh[(size_t)Vdim * Ddim];
__device__ __align__(16) __nv_bfloat16 g_Eth[(size_t)Ddim * Vdim];
__device__ __align__(16) __nv_bfloat16 g_Sb[(size_t)Mdim * Vdim];
__device__ float g_sums[Mdim];

#define SA 40   // smem row stride (bf16) = 80 B: conflict-free ldmatrix
static constexpr int TPB = 10240;     // one 128x32 bf16 plane (padded)

__device__ __forceinline__ uint32_t smem_u32(const void* p) {
    uint32_t a;
    asm("{ .reg .u64 t; cvta.to.shared.u64 t, %1; cvt.u32.u64 %0, t; }"
        : "=r"(a) : "l"(p));
    return a;
}
__device__ __forceinline__ void cpa16(uint32_t dst, const void* src, bool pred) {
    int sz = pred ? 16 : 0;
    asm volatile("cp.async.cg.shared.global [%0], [%1], 16, %2;"
                 :: "r"(dst), "l"(src), "r"(sz) : "memory");
}
template <int Ng>
__device__ __forceinline__ void cpa_wait() {
    asm volatile("cp.async.wait_group %0;" :: "n"(Ng) : "memory");
}
__device__ __forceinline__ void cpa_commit() {
    asm volatile("cp.async.commit_group;" ::: "memory");
}
// NOTE: not volatile — register-only op, let ptxas schedule around LDSM.
__device__ __forceinline__ void mma_bf16(float* c, const uint32_t* a, const uint32_t* b) {
    asm("mma.sync.aligned.m16n8k16.row.col.f32.bf16.bf16.f32 "
        "{%0,%1,%2,%3},{%4,%5,%6,%7},{%8,%9},{%0,%1,%2,%3};"
        : "+f"(c[0]), "+f"(c[1]), "+f"(c[2]), "+f"(c[3])
        : "r"(a[0]), "r"(a[1]), "r"(a[2]), "r"(a[3]), "r"(b[0]), "r"(b[1]));
}
__device__ __forceinline__ void ldm_x4(uint32_t& r0, uint32_t& r1,
                                       uint32_t& r2, uint32_t& r3, uint32_t addr) {
    asm volatile("ldmatrix.sync.aligned.m8n8.x4.shared.b16 {%0,%1,%2,%3}, [%4];"
                 : "=r"(r0), "=r"(r1), "=r"(r2), "=r"(r3) : "r"(addr));
}
__device__ __forceinline__ uint32_t packbf(float a, float b) {
    return (uint32_t)__bfloat16_as_ushort(__float2bfloat16_rn(a)) |
           ((uint32_t)__bfloat16_as_ushort(__float2bfloat16_rn(b)) << 16);
}
__device__ __forceinline__ void split2(float x, float y, uint32_t& hi, uint32_t& lo) {
    __nv_bfloat16 hx = __float2bfloat16_rn(x);
    __nv_bfloat16 hy = __float2bfloat16_rn(y);
    hi = (uint32_t)__bfloat16_as_ushort(hx) | ((uint32_t)__bfloat16_as_ushort(hy) << 16);
    lo = packbf(x - __bfloat162float(hx), y - __bfloat162float(hy));
}

// ---------------------------------------------------------------------------
// NT GEMM: C[m,n] = sum_k A[m,k]*B[n,k]. CTA 128x128x32, 8 warps of 64x32.
// PA/PB: bf16 planes per operand (2 = hi/lo split).
// Combos: hh (+ h*bl if PB==2) (+ al*bh if PA==2).
// EPI: 1 = tanh -> Cf fp32 + Cbh bf16 ; 2 = *(1/sums[m]) + R -> Cf ;
//      3 = exp -> Cbh bf16, atomicAdd row sums.
// 3-stage cp.async pipeline; warps 0-3 and 4-7 process the two k16 steps of
// each chunk in opposite order so SMSP-mates overlap LDSM with MMA.
// ---------------------------------------------------------------------------
template <int EPI, int PA, int PB>
__global__ __launch_bounds__(256, 2)
void gemm_nt(const __nv_bfloat16* __restrict__ Agh, const __nv_bfloat16* __restrict__ Agl,
             const __nv_bfloat16* __restrict__ Bgh, const __nv_bfloat16* __restrict__ Bgl,
             float* __restrict__ Cf, __nv_bfloat16* __restrict__ Cbh,
             const float* __restrict__ Rres, float* __restrict__ sums,
             int N, int K)
{
    constexpr int OFF_AH = 0;
    constexpr int OFF_AL = TPB;                 // valid iff PA==2
    constexpr int OFF_BH = PA * TPB;
    constexpr int OFF_BL = PA * TPB + TPB;      // valid iff PB==2
    constexpr int BUF    = (PA + PB) * TPB;

    extern __shared__ char smem[];
    const uint32_t sb = smem_u32(smem);

    const int tid  = threadIdx.x;
    const int wid  = tid >> 5;
    const int lane = tid & 31;
    const int g    = lane >> 2;
    const int tig  = lane & 3;
    const int wm   = wid & 1;
    const int wn   = wid >> 1;
    const int ksx  = (wid >> 2) & 1;   // SMSP-mate phase offset
    const int bm0  = blockIdx.y * 128;
    const int bn0  = blockIdx.x * 128;

    const int lrow = lane & 7;
    const int lb3  = (lane >> 3) & 1;
    const int lb4  = lane >> 4;
    const uint32_t a_lane = (uint32_t)(((wm * 64 + lb3 * 8 + lrow) * SA + lb4 * 8) * 2);
    const uint32_t b_lane = (uint32_t)(((wn * 32 + lb4 * 8 + lrow) * SA + lb3 * 8) * 2);

    float acc[4][4][4];
#pragma unroll
    for (int mi = 0; mi < 4; mi++)
#pragma unroll
        for (int ni = 0; ni < 4; ni++)
#pragma unroll
            for (int j = 0; j < 4; j++) acc[mi][ni][j] = 0.f;

    const int NC = (K + 31) >> 5;

    auto load_chunk = [&](int stage, int kt) {
        const uint32_t sbuf = sb + (uint32_t)(stage * BUF);
#pragma unroll
        for (int i = 0; i < 2; i++) {
            const int e   = tid + i * 256;
            const int row = e >> 2;
            const int kc  = (e & 3) << 3;
            const int gk  = kt + kc;
            const bool kok = gk < K;
            const uint32_t d = (uint32_t)(row * (SA * 2) + kc * 2);
            const size_t aoff = (size_t)(bm0 + row) * K + gk;
            cpa16(sbuf + OFF_AH + d, Agh + aoff, kok);
            if (PA == 2) cpa16(sbuf + OFF_AL + d, Agl + aoff, kok);
            const bool nok = ((bn0 + row) < N) && kok;
            const size_t boff = (size_t)(bn0 + row) * K + gk;
            cpa16(sbuf + OFF_BH + d, Bgh + boff, nok);
            if (PB == 2) cpa16(sbuf + OFF_BL + d, Bgl + boff, nok);
        }
        cpa_commit();
    };

    load_chunk(0, 0);
    load_chunk(1, 32);

    int stage = 0;
    for (int c = 0; c < NC; c++) {
        if (c + 1 < NC) cpa_wait<1>(); else cpa_wait<0>();
        __syncthreads();

        if (c + 2 < NC) {
            int ns = stage + 2; if (ns >= 3) ns -= 3;
            load_chunk(ns, (c + 2) << 5);
        }

        const uint32_t bufb = sb + (uint32_t)(stage * BUF);
#pragma unroll
        for (int ks0 = 0; ks0 < 2; ks0++) {
            const int ks = ks0 ^ ksx;          // stagger SMSP-mates
            const uint32_t ko = (uint32_t)(ks * 32);
            uint32_t ah[4][4], al[4][4], bh[4][2], bl[4][2];
#pragma unroll
            for (int mi = 0; mi < 4; mi++)
                ldm_x4(ah[mi][0], ah[mi][1], ah[mi][2], ah[mi][3],
                       bufb + OFF_AH + a_lane + (uint32_t)(mi * 16 * SA * 2) + ko);
            if (PA == 2) {
#pragma unroll
                for (int mi = 0; mi < 4; mi++)
                    ldm_x4(al[mi][0], al[mi][1], al[mi][2], al[mi][3],
                           bufb + OFF_AL + a_lane + (uint32_t)(mi * 16 * SA * 2) + ko);
            }
#pragma unroll
            for (int pp = 0; pp < 2; pp++)
                ldm_x4(bh[2 * pp][0], bh[2 * pp][1], bh[2 * pp + 1][0], bh[2 * pp + 1][1],
                       bufb + OFF_BH + b_lane + (uint32_t)(pp * 16 * SA * 2) + ko);
            if (PB == 2) {
#pragma unroll
                for (int pp = 0; pp < 2; pp++)
                    ldm_x4(bl[2 * pp][0], bl[2 * pp][1], bl[2 * pp + 1][0], bl[2 * pp + 1][1],
                           bufb + OFF_BL + b_lane + (uint32_t)(pp * 16 * SA * 2) + ko);
            }

#pragma unroll
            for (int mi = 0; mi < 4; mi++)
#pragma unroll
                for (int ni = 0; ni < 4; ni++)
                    mma_bf16(acc[mi][ni], ah[mi], bh[ni]);
            if (PB == 2) {
#pragma unroll
                for (int mi = 0; mi < 4; mi++)
#pragma unroll
                    for (int ni = 0; ni < 4; ni++)
                        mma_bf16(acc[mi][ni], ah[mi], bl[ni]);
            }
            if (PA == 2) {
#pragma unroll
                for (int mi = 0; mi < 4; mi++)
#pragma unroll
                    for (int ni = 0; ni < 4; ni++)
                        mma_bf16(acc[mi][ni], al[mi], bh[ni]);
            }
        }
        if (++stage == 3) stage = 0;
    }

    // ---- epilogue ----
#pragma unroll
    for (int mi = 0; mi < 4; mi++) {
        const int gm = bm0 + wm * 64 + mi * 16 + g;
        float s0 = 1.f, s1 = 1.f;
        if (EPI == 2) { s0 = 1.0f / sums[gm]; s1 = 1.0f / sums[gm + 8]; }
        float rs01 = 0.f, rs23 = 0.f;
#pragma unroll
        for (int ni = 0; ni < 4; ni++) {
            const int gn = bn0 + wn * 32 + ni * 8 + tig * 2;
            float* cc = acc[mi][ni];
            if (EPI == 3) {
                if (gn < N) {
                    const float e0 = __expf(cc[0]), e1 = __expf(cc[1]);
                    const float e2 = __expf(cc[2]), e3 = __expf(cc[3]);
                    rs01 += e0 + e1;
                    rs23 += e2 + e3;
                    *(uint32_t*)(Cbh + (size_t)gm * N + gn)       = packbf(e0, e1);
                    *(uint32_t*)(Cbh + (size_t)(gm + 8) * N + gn) = packbf(e2, e3);
                }
            } else if (gn < N) {
                float2 v0 = make_float2(cc[0], cc[1]);
                float2 v1 = make_float2(cc[2], cc[3]);
                if (EPI == 1) {
                    v0.x = tanhf(v0.x); v0.y = tanhf(v0.y);
                    v1.x = tanhf(v1.x); v1.y = tanhf(v1.y);
                    *(uint32_t*)(Cbh + (size_t)gm * N + gn)       = packbf(v0.x, v0.y);
                    *(uint32_t*)(Cbh + (size_t)(gm + 8) * N + gn) = packbf(v1.x, v1.y);
                }
                if (EPI == 2) {
                    const float2 r0 = *(const float2*)(Rres + (size_t)gm * N + gn);
                    const float2 r1 = *(const float2*)(Rres + (size_t)(gm + 8) * N + gn);
                    v0.x = v0.x * s0 + r0.x; v0.y = v0.y * s0 + r0.y;
                    v1.x = v1.x * s1 + r1.x; v1.y = v1.y * s1 + r1.y;
                }
                *(float2*)(Cf + (size_t)gm * N + gn)       = v0;
                *(float2*)(Cf + (size_t)(gm + 8) * N + gn) = v1;
            }
        }
        if (EPI == 3) {
            rs01 += __shfl_xor_sync(0xffffffffu, rs01, 1);
            rs01 += __shfl_xor_sync(0xffffffffu, rs01, 2);
            rs23 += __shfl_xor_sync(0xffffffffu, rs23, 1);
            rs23 += __shfl_xor_sync(0xffffffffu, rs23, 2);
            if (tig == 0) {
                atomicAdd(&sums[gm],     rs01);
                atomicAdd(&sums[gm + 8], rs23);
            }
        }
    }
}

// ---------------------------------------------------------------------------
__global__ __launch_bounds__(256)
void split_f32(const float* __restrict__ in, __nv_bfloat16* __restrict__ h,
               __nv_bfloat16* __restrict__ l, int n4)
{
    const int i = blockIdx.x * 256 + threadIdx.x;
    if (i < n4) {
        const float4 v = *(const float4*)(in + 4 * (size_t)i);
        uint32_t h0, l0, h1, l1;
        split2(v.x, v.y, h0, l0);
        split2(v.z, v.w, h1, l1);
        *(uint2*)(h + 4 * (size_t)i) = make_uint2(h0, h1);
        *(uint2*)(l + 4 * (size_t)i) = make_uint2(l0, l1);
    }
}

// E prep: Eh = bf16(E) [V,D]; Eth = bf16(E^T) [D,V]. Block (32,8).
__global__ __launch_bounds__(256)
void prep_E(const float* __restrict__ E,
            __nv_bfloat16* __restrict__ Eh, __nv_bfloat16* __restrict__ Eth,
            int V, int D)
{
    __shared__ float tile[32][33];
    const int d0 = blockIdx.x * 32;
    const int v0 = blockIdx.y * 32;
    const int tx = threadIdx.x, ty = threadIdx.y;

#pragma unroll
    for (int j = 0; j < 4; j++) {
        const int v = v0 + ty + 8 * j;
        const int d = d0 + tx;
        float val = 0.f;
        if (v < V) val = E[(size_t)v * D + d];
        tile[ty + 8 * j][tx] = val;
        if (v < V) Eh[(size_t)v * D + d] = __float2bfloat16_rn(val);
    }
    __syncthreads();
#pragma unroll
    for (int j = 0; j < 4; j++) {
        const int d = d0 + ty + 8 * j;
        const int v = v0 + tx;
        if (v < V)
            Eth[(size_t)d * V + v] = __float2bfloat16_rn(tile[tx][ty + 8 * j]);
    }
}

// ---------------------------------------------------------------------------
extern "C" void kernel_launch(void* const* d_in, const int* in_sizes, int n_in,
                              void* d_out, int out_size)
{
    (void)in_sizes; (void)n_in; (void)out_size;
    const float* x  = (const float*)d_in[0];   // [4096, 4000]
    const float* Wp = (const float*)d_in[1];   // [512, 4000]
    const float* E  = (const float*)d_in[2];   // [10000, 512]
    float* out = (float*)d_out;                // [4096, 512]

    __nv_bfloat16 *xh, *xl, *Wh, *Wl, *qh, *Eh, *Eth, *Sb;
    float* sums;
    cudaGetSymbolAddress((void**)&xh,  g_xh);
    cudaGetSymbolAddress((void**)&xl,  g_xl);
    cudaGetSymbolAddress((void**)&Wh,  g_Wh);
    cudaGetSymbolAddress((void**)&Wl,  g_Wl);
    cudaGetSymbolAddress((void**)&qh,  g_qh);
    cudaGetSymbolAddress((void**)&Eh,  g_Eh);
    cudaGetSymbolAddress((void**)&Eth, g_Eth);
    cudaGetSymbolAddress((void**)&Sb,  g_Sb);
    cudaGetSymbolAddress((void**)&sums, g_sums);

    constexpr int SM_K1 = 3 * 4 * TPB;   // 122880
    constexpr int SM_K2 = 3 * 2 * TPB;   // 61440
    cudaFuncSetAttribute((const void*)gemm_nt<1, 2, 2>,
                         cudaFuncAttributeMaxDynamicSharedMemorySize, SM_K1);
    cudaFuncSetAttribute((const void*)gemm_nt<3, 1, 1>,
                         cudaFuncAttributeMaxDynamicSharedMemorySize, SM_K2);
    cudaFuncSetAttribute((const void*)gemm_nt<2, 1, 1>,
                         cudaFuncAttributeMaxDynamicSharedMemorySize, SM_K2);

    cudaMemsetAsync(sums, 0, Mdim * sizeof(float));

    // prep
    split_f32<<<(Mdim * Cdim / 4 + 255) / 256, 256>>>(x, xh, xl, Mdim * Cdim / 4);
    split_f32<<<(Ddim * Cdim / 4 + 255) / 256, 256>>>(Wp, Wh, Wl, Ddim * Cdim / 4);
    prep_E<<<dim3(Ddim / 32, (Vdim + 31) / 32), dim3(32, 8)>>>(E, Eh, Eth, Vdim, Ddim);

    // K1: q = tanh(x @ W^T)   [N=512, K=4000], 3 combos
    gemm_nt<1, 2, 2><<<dim3(Ddim / 128, Mdim / 128), 256, SM_K1>>>(
        xh, xl, Wh, Wl, out, qh, nullptr, nullptr, Ddim, Cdim);

    // K2: Sb = bf16(exp(qh @ Eh^T)), sums = rowsum   [N=10000, K=512]
    gemm_nt<3, 1, 1><<<dim3((Vdim + 127) / 128, Mdim / 128), 256, SM_K2>>>(
        qh, nullptr, Eh, nullptr, nullptr, Sb, nullptr, sums, Vdim, Ddim);

    // K4: out = (Sb @ Eth^T) / sums + q   [N=512, K=10000]
    gemm_nt<2, 1, 1><<<dim3(Ddim / 128, Mdim / 128), 256, SM_K2>>>(
        Sb, nullptr, Eth, nullptr, out, nullptr, out, sums, Ddim, Vdim);
}

// round 10
// speedup vs baseline: 1.1539x; 1.0917x over previous
#include <cuda_runtime.h>
#include <cuda_bf16.h>
#include <cuda_fp16.h>
#include <math.h>
#include <stdint.h>

// ============================================================================
// SDEembedding on GB300 — HMMA NT pipeline, 3-stage cp.async.
//   prep:  x -> xh/xl (fp16 split) ; W -> Wh (fp16) ; E -> Eh, E^T -> Eth (bf16)
//   K1: q = tanh((xh+xl) @ Wh^T)   fp16, 2 combos, tile 128x128
//   K2: Sb = bf16(exp(qh @ Eh^T)), sums += rowsum   bf16, 1 combo
//       (no max pass: |logit| <= 51 since |q|<1, |E|<=0.1, D=512)
//   K4: out = (Sb @ Eth^T) * (1/sums) + q           bf16, 1 combo
// fp16 2-combo K1: 11-bit mantissa x-split against single fp16 W plane gives
// logit abs err ~1.6e-4 -> final rel err ~2.5e-4 (gate 1e-3).
// ============================================================================

static constexpr int Mdim = 4096, Ddim = 512, Cdim = 4000, Vdim = 10000;

__device__ __align__(16) __half        g_xh[(size_t)Mdim * Cdim];
__device__ __align__(16) __half        g_xl[(size_t)Mdim * Cdim];
__device__ __align__(16) __half        g_Wh[(size_t)Ddim * Cdim];
__device__ __align__(16) __nv_bfloat16 g_qh[(size_t)Mdim * Ddim];
__device__ __align__(16) __nv_bfloat16 g_Eh[(size_t)Vdim * Ddim];
__device__ __align__(16) __nv_bfloat16 g_Eth[(size_t)Ddim * Vdim];
__device__ __align__(16) __nv_bfloat16 g_Sb[(size_t)Mdim * Vdim];
__device__ float g_sums[Mdim];

#define SA 40   // smem row stride (16-bit elems) = 80 B: conflict-free ldmatrix
static constexpr int TPB = 10240;     // one 128x32 16-bit plane (padded)

__device__ __forceinline__ uint32_t smem_u32(const void* p) {
    uint32_t a;
    asm("{ .reg .u64 t; cvta.to.shared.u64 t, %1; cvt.u32.u64 %0, t; }"
        : "=r"(a) : "l"(p));
    return a;
}
__device__ __forceinline__ void cpa16(uint32_t dst, const void* src, bool pred) {
    int sz = pred ? 16 : 0;
    asm volatile("cp.async.cg.shared.global [%0], [%1], 16, %2;"
                 :: "r"(dst), "l"(src), "r"(sz) : "memory");
}
template <int Ng>
__device__ __forceinline__ void cpa_wait() {
    asm volatile("cp.async.wait_group %0;" :: "n"(Ng) : "memory");
}
__device__ __forceinline__ void cpa_commit() {
    asm volatile("cp.async.commit_group;" ::: "memory");
}
// FP16=0 -> bf16 inputs, FP16=1 -> fp16 inputs; fp32 accumulate either way.
template <int FP16>
__device__ __forceinline__ void mma_16(float* c, const uint32_t* a, const uint32_t* b) {
    if (FP16)
        asm("mma.sync.aligned.m16n8k16.row.col.f32.f16.f16.f32 "
            "{%0,%1,%2,%3},{%4,%5,%6,%7},{%8,%9},{%0,%1,%2,%3};"
            : "+f"(c[0]), "+f"(c[1]), "+f"(c[2]), "+f"(c[3])
            : "r"(a[0]), "r"(a[1]), "r"(a[2]), "r"(a[3]), "r"(b[0]), "r"(b[1]));
    else
        asm("mma.sync.aligned.m16n8k16.row.col.f32.bf16.bf16.f32 "
            "{%0,%1,%2,%3},{%4,%5,%6,%7},{%8,%9},{%0,%1,%2,%3};"
            : "+f"(c[0]), "+f"(c[1]), "+f"(c[2]), "+f"(c[3])
            : "r"(a[0]), "r"(a[1]), "r"(a[2]), "r"(a[3]), "r"(b[0]), "r"(b[1]));
}
__device__ __forceinline__ void ldm_x4(uint32_t& r0, uint32_t& r1,
                                       uint32_t& r2, uint32_t& r3, uint32_t addr) {
    asm volatile("ldmatrix.sync.aligned.m8n8.x4.shared.b16 {%0,%1,%2,%3}, [%4];"
                 : "=r"(r0), "=r"(r1), "=r"(r2), "=r"(r3) : "r"(addr));
}
__device__ __forceinline__ uint32_t packbf(float a, float b) {
    return (uint32_t)__bfloat16_as_ushort(__float2bfloat16_rn(a)) |
           ((uint32_t)__bfloat16_as_ushort(__float2bfloat16_rn(b)) << 16);
}

// ---------------------------------------------------------------------------
// NT GEMM: C[m,n] = sum_k A[m,k]*B[n,k]. CTA 128x128x32, 8 warps of 64x32.
// PA/PB: 16-bit planes per operand (2 = hi/lo split, 1 = single plane).
// Combos: Ah*Bh (+ Ah*Bl if PB==2) (+ Al*Bh if PA==2).
// EPI: 1 = tanh -> Cf fp32 + Cbh bf16 ; 2 = *(1/sums[m]) + R -> Cf ;
//      3 = exp -> Cbh bf16, atomicAdd row sums.  3-stage cp.async pipeline.
// ---------------------------------------------------------------------------
template <int EPI, int PA, int PB, int FP16>
__global__ __launch_bounds__(256, 2)
void gemm_nt(const void* __restrict__ Agh, const void* __restrict__ Agl,
             const void* __restrict__ Bgh, const void* __restrict__ Bgl,
             float* __restrict__ Cf, __nv_bfloat16* __restrict__ Cbh,
             const float* __restrict__ Rres, float* __restrict__ sums,
             int N, int K)
{
    constexpr int OFF_AH = 0;
    constexpr int OFF_AL = TPB;                 // valid iff PA==2
    constexpr int OFF_BH = PA * TPB;
    constexpr int OFF_BL = PA * TPB + TPB;      // valid iff PB==2
    constexpr int BUF    = (PA + PB) * TPB;

    extern __shared__ char smem[];
    const uint32_t sb = smem_u32(smem);

    const int tid  = threadIdx.x;
    const int wid  = tid >> 5;
    const int lane = tid & 31;
    const int g    = lane >> 2;
    const int tig  = lane & 3;
    const int wm   = wid & 1;
    const int wn   = wid >> 1;
    const int bm0  = blockIdx.y * 128;
    const int bn0  = blockIdx.x * 128;

    const int lrow = lane & 7;
    const int lb3  = (lane >> 3) & 1;
    const int lb4  = lane >> 4;
    const uint32_t a_lane = (uint32_t)(((wm * 64 + lb3 * 8 + lrow) * SA + lb4 * 8) * 2);
    const uint32_t b_lane = (uint32_t)(((wn * 32 + lb4 * 8 + lrow) * SA + lb3 * 8) * 2);

    float acc[4][4][4];
#pragma unroll
    for (int mi = 0; mi < 4; mi++)
#pragma unroll
        for (int ni = 0; ni < 4; ni++)
#pragma unroll
            for (int j = 0; j < 4; j++) acc[mi][ni][j] = 0.f;

    const int NC = (K + 31) >> 5;

    auto load_chunk = [&](int stage, int kt) {
        const uint32_t sbuf = sb + (uint32_t)(stage * BUF);
#pragma unroll
        for (int i = 0; i < 2; i++) {
            const int e   = tid + i * 256;
            const int row = e >> 2;
            const int kc  = (e & 3) << 3;
            const int gk  = kt + kc;
            const bool kok = gk < K;
            const uint32_t d = (uint32_t)(row * (SA * 2) + kc * 2);
            const size_t off = (size_t)(bm0 + row) * K + gk;
            cpa16(sbuf + OFF_AH + d, (const uint16_t*)Agh + off, kok);
            if (PA == 2) cpa16(sbuf + OFF_AL + d, (const uint16_t*)Agl + off, kok);
            const bool nok = ((bn0 + row) < N) && kok;
            const size_t boff = (size_t)(bn0 + row) * K + gk;
            cpa16(sbuf + OFF_BH + d, (const uint16_t*)Bgh + boff, nok);
            if (PB == 2) cpa16(sbuf + OFF_BL + d, (const uint16_t*)Bgl + boff, nok);
        }
        cpa_commit();
    };

    load_chunk(0, 0);
    load_chunk(1, 32);

    int stage = 0;
    for (int c = 0; c < NC; c++) {
        if (c + 1 < NC) cpa_wait<1>(); else cpa_wait<0>();
        __syncthreads();

        if (c + 2 < NC) {
            int ns = stage + 2; if (ns >= 3) ns -= 3;
            load_chunk(ns, (c + 2) << 5);
        }

        const uint32_t bufb = sb + (uint32_t)(stage * BUF);
#pragma unroll
        for (int ks = 0; ks < 2; ks++) {
            const uint32_t ko = (uint32_t)(ks * 32);
            uint32_t ah[4][4], al[4][4], bh[4][2], bl[4][2];
#pragma unroll
            for (int mi = 0; mi < 4; mi++)
                ldm_x4(ah[mi][0], ah[mi][1], ah[mi][2], ah[mi][3],
                       bufb + OFF_AH + a_lane + (uint32_t)(mi * 16 * SA * 2) + ko);
            if (PA == 2) {
#pragma unroll
                for (int mi = 0; mi < 4; mi++)
                    ldm_x4(al[mi][0], al[mi][1], al[mi][2], al[mi][3],
                           bufb + OFF_AL + a_lane + (uint32_t)(mi * 16 * SA * 2) + ko);
            }
#pragma unroll
            for (int pp = 0; pp < 2; pp++)
                ldm_x4(bh[2 * pp][0], bh[2 * pp][1], bh[2 * pp + 1][0], bh[2 * pp + 1][1],
                       bufb + OFF_BH + b_lane + (uint32_t)(pp * 16 * SA * 2) + ko);
            if (PB == 2) {
#pragma unroll
                for (int pp = 0; pp < 2; pp++)
                    ldm_x4(bl[2 * pp][0], bl[2 * pp][1], bl[2 * pp + 1][0], bl[2 * pp + 1][1],
                           bufb + OFF_BL + b_lane + (uint32_t)(pp * 16 * SA * 2) + ko);
            }

#pragma unroll
            for (int mi = 0; mi < 4; mi++)
#pragma unroll
                for (int ni = 0; ni < 4; ni++)
                    mma_16<FP16>(acc[mi][ni], ah[mi], bh[ni]);
            if (PB == 2) {
#pragma unroll
                for (int mi = 0; mi < 4; mi++)
#pragma unroll
                    for (int ni = 0; ni < 4; ni++)
                        mma_16<FP16>(acc[mi][ni], ah[mi], bl[ni]);
            }
            if (PA == 2) {
#pragma unroll
                for (int mi = 0; mi < 4; mi++)
#pragma unroll
                    for (int ni = 0; ni < 4; ni++)
                        mma_16<FP16>(acc[mi][ni], al[mi], bh[ni]);
            }
        }
        if (++stage == 3) stage = 0;
    }

    // ---- epilogue ----
#pragma unroll
    for (int mi = 0; mi < 4; mi++) {
        const int gm = bm0 + wm * 64 + mi * 16 + g;
        float s0 = 1.f, s1 = 1.f;
        if (EPI == 2) { s0 = 1.0f / sums[gm]; s1 = 1.0f / sums[gm + 8]; }
        float rs01 = 0.f, rs23 = 0.f;
#pragma unroll
        for (int ni = 0; ni < 4; ni++) {
            const int gn = bn0 + wn * 32 + ni * 8 + tig * 2;
            float* cc = acc[mi][ni];
            if (EPI == 3) {
                if (gn < N) {
                    const float e0 = __expf(cc[0]), e1 = __expf(cc[1]);
                    const float e2 = __expf(cc[2]), e3 = __expf(cc[3]);
                    rs01 += e0 + e1;
                    rs23 += e2 + e3;
                    *(uint32_t*)(Cbh + (size_t)gm * N + gn)       = packbf(e0, e1);
                    *(uint32_t*)(Cbh + (size_t)(gm + 8) * N + gn) = packbf(e2, e3);
                }
            } else if (gn < N) {
                float2 v0 = make_float2(cc[0], cc[1]);
                float2 v1 = make_float2(cc[2], cc[3]);
                if (EPI == 1) {
                    v0.x = tanhf(v0.x); v0.y = tanhf(v0.y);
                    v1.x = tanhf(v1.x); v1.y = tanhf(v1.y);
                    *(uint32_t*)(Cbh + (size_t)gm * N + gn)       = packbf(v0.x, v0.y);
                    *(uint32_t*)(Cbh + (size_t)(gm + 8) * N + gn) = packbf(v1.x, v1.y);
                }
                if (EPI == 2) {
                    const float2 r0 = *(const float2*)(Rres + (size_t)gm * N + gn);
                    const float2 r1 = *(const float2*)(Rres + (size_t)(gm + 8) * N + gn);
                    v0.x = v0.x * s0 + r0.x; v0.y = v0.y * s0 + r0.y;
                    v1.x = v1.x * s1 + r1.x; v1.y = v1.y * s1 + r1.y;
                }
                *(float2*)(Cf + (size_t)gm * N + gn)       = v0;
                *(float2*)(Cf + (size_t)(gm + 8) * N + gn) = v1;
            }
        }
        if (EPI == 3) {
            rs01 += __shfl_xor_sync(0xffffffffu, rs01, 1);
            rs01 += __shfl_xor_sync(0xffffffffu, rs01, 2);
            rs23 += __shfl_xor_sync(0xffffffffu, rs23, 1);
            rs23 += __shfl_xor_sync(0xffffffffu, rs23, 2);
            if (tig == 0) {
                atomicAdd(&sums[gm],     rs01);
                atomicAdd(&sums[gm + 8], rs23);
            }
        }
    }
}

// ---------------------------------------------------------------------------
// fp16 hi/lo split of fp32 input (x plane).
// ---------------------------------------------------------------------------
__global__ __launch_bounds__(256)
void split_f32_h(const float* __restrict__ in, __half* __restrict__ h,
                 __half* __restrict__ l, int n4)
{
    const int i = blockIdx.x * 256 + threadIdx.x;
    if (i < n4) {
        const float4 v = *(const float4*)(in + 4 * (size_t)i);
        const float vv[4] = { v.x, v.y, v.z, v.w };
        __half hh[4], ll[4];
#pragma unroll
        for (int j = 0; j < 4; j++) {
            hh[j] = __float2half_rn(vv[j]);
            ll[j] = __float2half_rn(vv[j] - __half2float(hh[j]));
        }
        *(uint2*)(h + 4 * (size_t)i) = *(const uint2*)hh;
        *(uint2*)(l + 4 * (size_t)i) = *(const uint2*)ll;
    }
}

// fp32 -> single fp16 plane (W).
__global__ __launch_bounds__(256)
void conv_f16(const float* __restrict__ in, __half* __restrict__ h, int n4)
{
    const int i = blockIdx.x * 256 + threadIdx.x;
    if (i < n4) {
        const float4 v = *(const float4*)(in + 4 * (size_t)i);
        __half hh[4] = { __float2half_rn(v.x), __float2half_rn(v.y),
                         __float2half_rn(v.z), __float2half_rn(v.w) };
        *(uint2*)(h + 4 * (size_t)i) = *(const uint2*)hh;
    }
}

// E prep: Eh = bf16(E) [V,D]; Eth = bf16(E^T) [D,V]. Block (32,8).
__global__ __launch_bounds__(256)
void prep_E(const float* __restrict__ E,
            __nv_bfloat16* __restrict__ Eh, __nv_bfloat16* __restrict__ Eth,
            int V, int D)
{
    __shared__ float tile[32][33];
    const int d0 = blockIdx.x * 32;
    const int v0 = blockIdx.y * 32;
    const int tx = threadIdx.x, ty = threadIdx.y;

#pragma unroll
    for (int j = 0; j < 4; j++) {
        const int v = v0 + ty + 8 * j;
        const int d = d0 + tx;
        float val = 0.f;
        if (v < V) val = E[(size_t)v * D + d];
        tile[ty + 8 * j][tx] = val;
        if (v < V) Eh[(size_t)v * D + d] = __float2bfloat16_rn(val);
    }
    __syncthreads();
#pragma unroll
    for (int j = 0; j < 4; j++) {
        const int d = d0 + ty + 8 * j;
        const int v = v0 + tx;
        if (v < V)
            Eth[(size_t)d * V + v] = __float2bfloat16_rn(tile[tx][ty + 8 * j]);
    }
}

// ---------------------------------------------------------------------------
extern "C" void kernel_launch(void* const* d_in, const int* in_sizes, int n_in,
                              void* d_out, int out_size)
{
    (void)in_sizes; (void)n_in; (void)out_size;
    const float* x  = (const float*)d_in[0];   // [4096, 4000]
    const float* Wp = (const float*)d_in[1];   // [512, 4000]
    const float* E  = (const float*)d_in[2];   // [10000, 512]
    float* out = (float*)d_out;                // [4096, 512]

    __half *xh, *xl, *Wh;
    __nv_bfloat16 *qh, *Eh, *Eth, *Sb;
    float* sums;
    cudaGetSymbolAddress((void**)&xh,  g_xh);
    cudaGetSymbolAddress((void**)&xl,  g_xl);
    cudaGetSymbolAddress((void**)&Wh,  g_Wh);
    cudaGetSymbolAddress((void**)&qh,  g_qh);
    cudaGetSymbolAddress((void**)&Eh,  g_Eh);
    cudaGetSymbolAddress((void**)&Eth, g_Eth);
    cudaGetSymbolAddress((void**)&Sb,  g_Sb);
    cudaGetSymbolAddress((void**)&sums, g_sums);

    // K1: PA=2 PB=1 fp16 -> stage = 3*10240 = 30720; 3 stages = 92160
    // K2/K4: PA=1 PB=1 bf16 -> stage = 2*10240 = 20480; 3 stages = 61440
    constexpr int SM_K1 = 3 * 3 * TPB;
    constexpr int SM_K2 = 3 * 2 * TPB;
    cudaFuncSetAttribute((const void*)gemm_nt<1, 2, 1, 1>,
                         cudaFuncAttributeMaxDynamicSharedMemorySize, SM_K1);
    cudaFuncSetAttribute((const void*)gemm_nt<3, 1, 1, 0>,
                         cudaFuncAttributeMaxDynamicSharedMemorySize, SM_K2);
    cudaFuncSetAttribute((const void*)gemm_nt<2, 1, 1, 0>,
                         cudaFuncAttributeMaxDynamicSharedMemorySize, SM_K2);

    cudaMemsetAsync(sums, 0, Mdim * sizeof(float));

    // prep
    split_f32_h<<<(Mdim * Cdim / 4 + 255) / 256, 256>>>(x, xh, xl, Mdim * Cdim / 4);
    conv_f16<<<(Ddim * Cdim / 4 + 255) / 256, 256>>>(Wp, Wh, Ddim * Cdim / 4);
    prep_E<<<dim3(Ddim / 32, (Vdim + 31) / 32), dim3(32, 8)>>>(E, Eh, Eth, Vdim, Ddim);

    // K1: q = tanh(x @ W^T)   [N=512, K=4000], fp16 2 combos
    gemm_nt<1, 2, 1, 1><<<dim3(Ddim / 128, Mdim / 128), 256, SM_K1>>>(
        xh, xl, Wh, nullptr, out, qh, nullptr, nullptr, Ddim, Cdim);

    // K2: Sb = bf16(exp(qh @ Eh^T)), sums = rowsum   [N=10000, K=512]
    gemm_nt<3, 1, 1, 0><<<dim3((Vdim + 127) / 128, Mdim / 128), 256, SM_K2>>>(
        qh, nullptr, Eh, nullptr, nullptr, Sb, nullptr, sums, Vdim, Ddim);

    // K4: out = (Sb @ Eth^T) / sums + q   [N=512, K=10000]
    gemm_nt<2, 1, 1, 0><<<dim3(Ddim / 128, Mdim / 128), 256, SM_K2>>>(
        Sb, nullptr, Eth, nullptr, out, nullptr, out, sums, Ddim, Vdim);
}

// round 11
// speedup vs baseline: 1.2835x; 1.1123x over previous
#include <cuda_runtime.h>
#include <cuda_bf16.h>
#include <cuda_fp16.h>
#include <math.h>
#include <stdint.h>

// ============================================================================
// SDEembedding on GB300 — HMMA NT pipeline, 3-stage cp.async.
//   prep:  x -> xh (fp16) ; W -> Wh (fp16) ; E -> Eh, E^T -> Eth (bf16)
//   K1: q = tanh(xh @ Wh^T)         fp16, 1 combo, tile 128x128
//   K2: Sb = bf16(exp(qh @ Eh^T)), sums += rowsum   bf16, 1 combo
//       (no max pass: |logit| <= 51 since |q|<1, |E|<=0.1, D=512)
//   K4: out = (Sb @ Eth^T) * (1/sums) + q           bf16, 1 combo
// Precision: fp16 x and W each contribute ~2.2e-4 rel err to q ->
// combined ~3.1e-4 final (gate 1e-3). K2/K4 bf16 contribution ~1e-5.
// ============================================================================

static constexpr int Mdim = 4096, Ddim = 512, Cdim = 4000, Vdim = 10000;

__device__ __align__(16) __half        g_xh[(size_t)Mdim * Cdim];
__device__ __align__(16) __half        g_Wh[(size_t)Ddim * Cdim];
__device__ __align__(16) __nv_bfloat16 g_qh[(size_t)Mdim * Ddim];
__device__ __align__(16) __nv_bfloat16 g_Eh[(size_t)Vdim * Ddim];
__device__ __align__(16) __nv_bfloat16 g_Eth[(size_t)Ddim * Vdim];
__device__ __align__(16) __nv_bfloat16 g_Sb[(size_t)Mdim * Vdim];
__device__ float g_sums[Mdim];

#define SA 40   // smem row stride (16-bit elems) = 80 B: conflict-free ldmatrix
static constexpr int TPB = 10240;     // one 128x32 16-bit plane (padded)

__device__ __forceinline__ uint32_t smem_u32(const void* p) {
    uint32_t a;
    asm("{ .reg .u64 t; cvta.to.shared.u64 t, %1; cvt.u32.u64 %0, t; }"
        : "=r"(a) : "l"(p));
    return a;
}
__device__ __forceinline__ void cpa16(uint32_t dst, const void* src, bool pred) {
    int sz = pred ? 16 : 0;
    asm volatile("cp.async.cg.shared.global [%0], [%1], 16, %2;"
                 :: "r"(dst), "l"(src), "r"(sz) : "memory");
}
template <int Ng>
__device__ __forceinline__ void cpa_wait() {
    asm volatile("cp.async.wait_group %0;" :: "n"(Ng) : "memory");
}
__device__ __forceinline__ void cpa_commit() {
    asm volatile("cp.async.commit_group;" ::: "memory");
}
// FP16=0 -> bf16 inputs, FP16=1 -> fp16 inputs; fp32 accumulate either way.
template <int FP16>
__device__ __forceinline__ void mma_16(float* c, const uint32_t* a, const uint32_t* b) {
    if (FP16)
        asm("mma.sync.aligned.m16n8k16.row.col.f32.f16.f16.f32 "
            "{%0,%1,%2,%3},{%4,%5,%6,%7},{%8,%9},{%0,%1,%2,%3};"
            : "+f"(c[0]), "+f"(c[1]), "+f"(c[2]), "+f"(c[3])
            : "r"(a[0]), "r"(a[1]), "r"(a[2]), "r"(a[3]), "r"(b[0]), "r"(b[1]));
    else
        asm("mma.sync.aligned.m16n8k16.row.col.f32.bf16.bf16.f32 "
            "{%0,%1,%2,%3},{%4,%5,%6,%7},{%8,%9},{%0,%1,%2,%3};"
            : "+f"(c[0]), "+f"(c[1]), "+f"(c[2]), "+f"(c[3])
            : "r"(a[0]), "r"(a[1]), "r"(a[2]), "r"(a[3]), "r"(b[0]), "r"(b[1]));
}
__device__ __forceinline__ void ldm_x4(uint32_t& r0, uint32_t& r1,
                                       uint32_t& r2, uint32_t& r3, uint32_t addr) {
    asm volatile("ldmatrix.sync.aligned.m8n8.x4.shared.b16 {%0,%1,%2,%3}, [%4];"
                 : "=r"(r0), "=r"(r1), "=r"(r2), "=r"(r3) : "r"(addr));
}
__device__ __forceinline__ uint32_t packbf(float a, float b) {
    return (uint32_t)__bfloat16_as_ushort(__float2bfloat16_rn(a)) |
           ((uint32_t)__bfloat16_as_ushort(__float2bfloat16_rn(b)) << 16);
}

// ---------------------------------------------------------------------------
// NT GEMM: C[m,n] = sum_k A[m,k]*B[n,k]. CTA 128x128x32, 8 warps of 64x32.
// PA/PB: 16-bit planes per operand (2 = hi/lo split, 1 = single plane).
// Combos: Ah*Bh (+ Ah*Bl if PB==2) (+ Al*Bh if PA==2).
// EPI: 1 = tanh -> Cf fp32 + Cbh bf16 ; 2 = *(1/sums[m]) + R -> Cf ;
//      3 = exp -> Cbh bf16, atomicAdd row sums.  3-stage cp.async pipeline.
// ---------------------------------------------------------------------------
template <int EPI, int PA, int PB, int FP16>
__global__ __launch_bounds__(256, 2)
void gemm_nt(const void* __restrict__ Agh, const void* __restrict__ Agl,
             const void* __restrict__ Bgh, const void* __restrict__ Bgl,
             float* __restrict__ Cf, __nv_bfloat16* __restrict__ Cbh,
             const float* __restrict__ Rres, float* __restrict__ sums,
             int N, int K)
{
    constexpr int OFF_AH = 0;
    constexpr int OFF_AL = TPB;                 // valid iff PA==2
    constexpr int OFF_BH = PA * TPB;
    constexpr int OFF_BL = PA * TPB + TPB;      // valid iff PB==2
    constexpr int BUF    = (PA + PB) * TPB;

    extern __shared__ char smem[];
    const uint32_t sb = smem_u32(smem);

    const int tid  = threadIdx.x;
    const int wid  = tid >> 5;
    const int lane = tid & 31;
    const int g    = lane >> 2;
    const int tig  = lane & 3;
    const int wm   = wid & 1;
    const int wn   = wid >> 1;
    const int bm0  = blockIdx.y * 128;
    const int bn0  = blockIdx.x * 128;

    const int lrow = lane & 7;
    const int lb3  = (lane >> 3) & 1;
    const int lb4  = lane >> 4;
    const uint32_t a_lane = (uint32_t)(((wm * 64 + lb3 * 8 + lrow) * SA + lb4 * 8) * 2);
    const uint32_t b_lane = (uint32_t)(((wn * 32 + lb4 * 8 + lrow) * SA + lb3 * 8) * 2);

    float acc[4][4][4];
#pragma unroll
    for (int mi = 0; mi < 4; mi++)
#pragma unroll
        for (int ni = 0; ni < 4; ni++)
#pragma unroll
            for (int j = 0; j < 4; j++) acc[mi][ni][j] = 0.f;

    const int NC = (K + 31) >> 5;

    auto load_chunk = [&](int stage, int kt) {
        const uint32_t sbuf = sb + (uint32_t)(stage * BUF);
#pragma unroll
        for (int i = 0; i < 2; i++) {
            const int e   = tid + i * 256;
            const int row = e >> 2;
            const int kc  = (e & 3) << 3;
            const int gk  = kt + kc;
            const bool kok = gk < K;
            const uint32_t d = (uint32_t)(row * (SA * 2) + kc * 2);
            const size_t off = (size_t)(bm0 + row) * K + gk;
            cpa16(sbuf + OFF_AH + d, (const uint16_t*)Agh + off, kok);
            if (PA == 2) cpa16(sbuf + OFF_AL + d, (const uint16_t*)Agl + off, kok);
            const bool nok = ((bn0 + row) < N) && kok;
            const size_t boff = (size_t)(bn0 + row) * K + gk;
            cpa16(sbuf + OFF_BH + d, (const uint16_t*)Bgh + boff, nok);
            if (PB == 2) cpa16(sbuf + OFF_BL + d, (const uint16_t*)Bgl + boff, nok);
        }
        cpa_commit();
    };

    load_chunk(0, 0);
    load_chunk(1, 32);

    int stage = 0;
    for (int c = 0; c < NC; c++) {
        if (c + 1 < NC) cpa_wait<1>(); else cpa_wait<0>();
        __syncthreads();

        if (c + 2 < NC) {
            int ns = stage + 2; if (ns >= 3) ns -= 3;
            load_chunk(ns, (c + 2) << 5);
        }

        const uint32_t bufb = sb + (uint32_t)(stage * BUF);
#pragma unroll
        for (int ks = 0; ks < 2; ks++) {
            const uint32_t ko = (uint32_t)(ks * 32);
            uint32_t ah[4][4], al[4][4], bh[4][2], bl[4][2];
#pragma unroll
            for (int mi = 0; mi < 4; mi++)
                ldm_x4(ah[mi][0], ah[mi][1], ah[mi][2], ah[mi][3],
                       bufb + OFF_AH + a_lane + (uint32_t)(mi * 16 * SA * 2) + ko);
            if (PA == 2) {
#pragma unroll
                for (int mi = 0; mi < 4; mi++)
                    ldm_x4(al[mi][0], al[mi][1], al[mi][2], al[mi][3],
                           bufb + OFF_AL + a_lane + (uint32_t)(mi * 16 * SA * 2) + ko);
            }
#pragma unroll
            for (int pp = 0; pp < 2; pp++)
                ldm_x4(bh[2 * pp][0], bh[2 * pp][1], bh[2 * pp + 1][0], bh[2 * pp + 1][1],
                       bufb + OFF_BH + b_lane + (uint32_t)(pp * 16 * SA * 2) + ko);
            if (PB == 2) {
#pragma unroll
                for (int pp = 0; pp < 2; pp++)
                    ldm_x4(bl[2 * pp][0], bl[2 * pp][1], bl[2 * pp + 1][0], bl[2 * pp + 1][1],
                           bufb + OFF_BL + b_lane + (uint32_t)(pp * 16 * SA * 2) + ko);
            }

#pragma unroll
            for (int mi = 0; mi < 4; mi++)
#pragma unroll
                for (int ni = 0; ni < 4; ni++)
                    mma_16<FP16>(acc[mi][ni], ah[mi], bh[ni]);
            if (PB == 2) {
#pragma unroll
                for (int mi = 0; mi < 4; mi++)
#pragma unroll
                    for (int ni = 0; ni < 4; ni++)
                        mma_16<FP16>(acc[mi][ni], ah[mi], bl[ni]);
            }
            if (PA == 2) {
#pragma unroll
                for (int mi = 0; mi < 4; mi++)
#pragma unroll
                    for (int ni = 0; ni < 4; ni++)
                        mma_16<FP16>(acc[mi][ni], al[mi], bh[ni]);
            }
        }
        if (++stage == 3) stage = 0;
    }

    // ---- epilogue ----
#pragma unroll
    for (int mi = 0; mi < 4; mi++) {
        const int gm = bm0 + wm * 64 + mi * 16 + g;
        float s0 = 1.f, s1 = 1.f;
        if (EPI == 2) { s0 = 1.0f / sums[gm]; s1 = 1.0f / sums[gm + 8]; }
        float rs01 = 0.f, rs23 = 0.f;
#pragma unroll
        for (int ni = 0; ni < 4; ni++) {
            const int gn = bn0 + wn * 32 + ni * 8 + tig * 2;
            float* cc = acc[mi][ni];
            if (EPI == 3) {
                if (gn < N) {
                    const float e0 = __expf(cc[0]), e1 = __expf(cc[1]);
                    const float e2 = __expf(cc[2]), e3 = __expf(cc[3]);
                    rs01 += e0 + e1;
                    rs23 += e2 + e3;
                    *(uint32_t*)(Cbh + (size_t)gm * N + gn)       = packbf(e0, e1);
                    *(uint32_t*)(Cbh + (size_t)(gm + 8) * N + gn) = packbf(e2, e3);
                }
            } else if (gn < N) {
                float2 v0 = make_float2(cc[0], cc[1]);
                float2 v1 = make_float2(cc[2], cc[3]);
                if (EPI == 1) {
                    v0.x = tanhf(v0.x); v0.y = tanhf(v0.y);
                    v1.x = tanhf(v1.x); v1.y = tanhf(v1.y);
                    *(uint32_t*)(Cbh + (size_t)gm * N + gn)       = packbf(v0.x, v0.y);
                    *(uint32_t*)(Cbh + (size_t)(gm + 8) * N + gn) = packbf(v1.x, v1.y);
                }
                if (EPI == 2) {
                    const float2 r0 = *(const float2*)(Rres + (size_t)gm * N + gn);
                    const float2 r1 = *(const float2*)(Rres + (size_t)(gm + 8) * N + gn);
                    v0.x = v0.x * s0 + r0.x; v0.y = v0.y * s0 + r0.y;
                    v1.x = v1.x * s1 + r1.x; v1.y = v1.y * s1 + r1.y;
                }
                *(float2*)(Cf + (size_t)gm * N + gn)       = v0;
                *(float2*)(Cf + (size_t)(gm + 8) * N + gn) = v1;
            }
        }
        if (EPI == 3) {
            rs01 += __shfl_xor_sync(0xffffffffu, rs01, 1);
            rs01 += __shfl_xor_sync(0xffffffffu, rs01, 2);
            rs23 += __shfl_xor_sync(0xffffffffu, rs23, 1);
            rs23 += __shfl_xor_sync(0xffffffffu, rs23, 2);
            if (tig == 0) {
                atomicAdd(&sums[gm],     rs01);
                atomicAdd(&sums[gm + 8], rs23);
            }
        }
    }
}

// ---------------------------------------------------------------------------
// fp32 -> single fp16 plane (x and W).
// ---------------------------------------------------------------------------
__global__ __launch_bounds__(256)
void conv_f16(const float* __restrict__ in, __half* __restrict__ h, int n4)
{
    const int i = blockIdx.x * 256 + threadIdx.x;
    if (i < n4) {
        const float4 v = *(const float4*)(in + 4 * (size_t)i);
        __half hh[4] = { __float2half_rn(v.x), __float2half_rn(v.y),
                         __float2half_rn(v.z), __float2half_rn(v.w) };
        *(uint2*)(h + 4 * (size_t)i) = *(const uint2*)hh;
    }
}

// E prep: Eh = bf16(E) [V,D]; Eth = bf16(E^T) [D,V]. Block (32,8).
__global__ __launch_bounds__(256)
void prep_E(const float* __restrict__ E,
            __nv_bfloat16* __restrict__ Eh, __nv_bfloat16* __restrict__ Eth,
            int V, int D)
{
    __shared__ float tile[32][33];
    const int d0 = blockIdx.x * 32;
    const int v0 = blockIdx.y * 32;
    const int tx = threadIdx.x, ty = threadIdx.y;

#pragma unroll
    for (int j = 0; j < 4; j++) {
        const int v = v0 + ty + 8 * j;
        const int d = d0 + tx;
        float val = 0.f;
        if (v < V) val = E[(size_t)v * D + d];
        tile[ty + 8 * j][tx] = val;
        if (v < V) Eh[(size_t)v * D + d] = __float2bfloat16_rn(val);
    }
    __syncthreads();
#pragma unroll
    for (int j = 0; j < 4; j++) {
        const int d = d0 + ty + 8 * j;
        const int v = v0 + tx;
        if (v < V)
            Eth[(size_t)d * V + v] = __float2bfloat16_rn(tile[tx][ty + 8 * j]);
    }
}

// ---------------------------------------------------------------------------
extern "C" void kernel_launch(void* const* d_in, const int* in_sizes, int n_in,
                              void* d_out, int out_size)
{
    (void)in_sizes; (void)n_in; (void)out_size;
    const float* x  = (const float*)d_in[0];   // [4096, 4000]
    const float* Wp = (const float*)d_in[1];   // [512, 4000]
    const float* E  = (const float*)d_in[2];   // [10000, 512]
    float* out = (float*)d_out;                // [4096, 512]

    __half *xh, *Wh;
    __nv_bfloat16 *qh, *Eh, *Eth, *Sb;
    float* sums;
    cudaGetSymbolAddress((void**)&xh,  g_xh);
    cudaGetSymbolAddress((void**)&Wh,  g_Wh);
    cudaGetSymbolAddress((void**)&qh,  g_qh);
    cudaGetSymbolAddress((void**)&Eh,  g_Eh);
    cudaGetSymbolAddress((void**)&Eth, g_Eth);
    cudaGetSymbolAddress((void**)&Sb,  g_Sb);
    cudaGetSymbolAddress((void**)&sums, g_sums);

    // All GEMMs: PA=1 PB=1 -> stage = 2*10240 = 20480; 3 stages = 61440 (2/SM)
    constexpr int SM_G = 3 * 2 * TPB;
    cudaFuncSetAttribute((const void*)gemm_nt<1, 1, 1, 1>,
                         cudaFuncAttributeMaxDynamicSharedMemorySize, SM_G);
    cudaFuncSetAttribute((const void*)gemm_nt<3, 1, 1, 0>,
                         cudaFuncAttributeMaxDynamicSharedMemorySize, SM_G);
    cudaFuncSetAttribute((const void*)gemm_nt<2, 1, 1, 0>,
                         cudaFuncAttributeMaxDynamicSharedMemorySize, SM_G);

    cudaMemsetAsync(sums, 0, Mdim * sizeof(float));

    // prep
    conv_f16<<<(Mdim * Cdim / 4 + 255) / 256, 256>>>(x, xh, Mdim * Cdim / 4);
    conv_f16<<<(Ddim * Cdim / 4 + 255) / 256, 256>>>(Wp, Wh, Ddim * Cdim / 4);
    prep_E<<<dim3(Ddim / 32, (Vdim + 31) / 32), dim3(32, 8)>>>(E, Eh, Eth, Vdim, Ddim);

    // K1: q = tanh(x @ W^T)   [N=512, K=4000], fp16 1 combo
    gemm_nt<1, 1, 1, 1><<<dim3(Ddim / 128, Mdim / 128), 256, SM_G>>>(
        xh, nullptr, Wh, nullptr, out, qh, nullptr, nullptr, Ddim, Cdim);

    // K2: Sb = bf16(exp(qh @ Eh^T)), sums = rowsum   [N=10000, K=512]
    gemm_nt<3, 1, 1, 0><<<dim3((Vdim + 127) / 128, Mdim / 128), 256, SM_G>>>(
        qh, nullptr, Eh, nullptr, nullptr, Sb, nullptr, sums, Vdim, Ddim);

    // K4: out = (Sb @ Eth^T) / sums + q   [N=512, K=10000]
    gemm_nt<2, 1, 1, 0><<<dim3(Ddim / 128, Mdim / 128), 256, SM_G>>>(
        Sb, nullptr, Eth, nullptr, out, nullptr, out, sums, Ddim, Vdim);
}

// round 12
// speedup vs baseline: 1.3193x; 1.0279x over previous
#include <cuda_runtime.h>
#include <cuda_bf16.h>
#include <cuda_fp16.h>
#include <math.h>
#include <stdint.h>

// ============================================================================
// SDEembedding on GB300 — HMMA NT pipeline, 3-stage cp.async, split-K.
//   prep:  x -> xh (fp16) ; W -> Wh (fp16) ; E -> Eh, E^T -> Eth (bf16)
//   K1: p = x @ W^T (split-K 2, fp32 partials) ; combine_q: q=tanh(p0+p1)
//   K2: Sb = bf16(exp(qh @ Eh^T)), sums += rowsum  (grid 2528, 1 combo)
//   K4: p = Sb @ Eth^T (split-K 2) ; combine_o: out=(p0+p1)/sums + q
// Split-K doubles the grid for the two N=512 GEMMs (128 CTAs -> 256) so SMs
// get co-resident CTAs to hide LDSM/issue bubbles — K2's measured advantage.
// ============================================================================

static constexpr int Mdim = 4096, Ddim = 512, Cdim = 4000, Vdim = 10000;

__device__ __align__(16) __half        g_xh[(size_t)Mdim * Cdim];
__device__ __align__(16) __half        g_Wh[(size_t)Ddim * Cdim];
__device__ __align__(16) __nv_bfloat16 g_qh[(size_t)Mdim * Ddim];
__device__ __align__(16) __nv_bfloat16 g_Eh[(size_t)Vdim * Ddim];
__device__ __align__(16) __nv_bfloat16 g_Eth[(size_t)Ddim * Vdim];
__device__ __align__(16) __nv_bfloat16 g_Sb[(size_t)Mdim * Vdim];
__device__ __align__(16) float g_part[2ull * Mdim * Ddim];   // split-K partials
__device__ float g_sums[Mdim];

#define SA 40   // smem row stride (16-bit elems) = 80 B: conflict-free ldmatrix
static constexpr int TPB = 10240;     // one 128x32 16-bit plane (padded)

__device__ __forceinline__ uint32_t smem_u32(const void* p) {
    uint32_t a;
    asm("{ .reg .u64 t; cvta.to.shared.u64 t, %1; cvt.u32.u64 %0, t; }"
        : "=r"(a) : "l"(p));
    return a;
}
__device__ __forceinline__ void cpa16(uint32_t dst, const void* src, bool pred) {
    int sz = pred ? 16 : 0;
    asm volatile("cp.async.cg.shared.global [%0], [%1], 16, %2;"
                 :: "r"(dst), "l"(src), "r"(sz) : "memory");
}
template <int Ng>
__device__ __forceinline__ void cpa_wait() {
    asm volatile("cp.async.wait_group %0;" :: "n"(Ng) : "memory");
}
__device__ __forceinline__ void cpa_commit() {
    asm volatile("cp.async.commit_group;" ::: "memory");
}
template <int FP16>
__device__ __forceinline__ void mma_16(float* c, const uint32_t* a, const uint32_t* b) {
    if (FP16)
        asm("mma.sync.aligned.m16n8k16.row.col.f32.f16.f16.f32 "
            "{%0,%1,%2,%3},{%4,%5,%6,%7},{%8,%9},{%0,%1,%2,%3};"
            : "+f"(c[0]), "+f"(c[1]), "+f"(c[2]), "+f"(c[3])
            : "r"(a[0]), "r"(a[1]), "r"(a[2]), "r"(a[3]), "r"(b[0]), "r"(b[1]));
    else
        asm("mma.sync.aligned.m16n8k16.row.col.f32.bf16.bf16.f32 "
            "{%0,%1,%2,%3},{%4,%5,%6,%7},{%8,%9},{%0,%1,%2,%3};"
            : "+f"(c[0]), "+f"(c[1]), "+f"(c[2]), "+f"(c[3])
            : "r"(a[0]), "r"(a[1]), "r"(a[2]), "r"(a[3]), "r"(b[0]), "r"(b[1]));
}
__device__ __forceinline__ void ldm_x4(uint32_t& r0, uint32_t& r1,
                                       uint32_t& r2, uint32_t& r3, uint32_t addr) {
    asm volatile("ldmatrix.sync.aligned.m8n8.x4.shared.b16 {%0,%1,%2,%3}, [%4];"
                 : "=r"(r0), "=r"(r1), "=r"(r2), "=r"(r3) : "r"(addr));
}
__device__ __forceinline__ uint32_t packbf(float a, float b) {
    return (uint32_t)__bfloat16_as_ushort(__float2bfloat16_rn(a)) |
           ((uint32_t)__bfloat16_as_ushort(__float2bfloat16_rn(b)) << 16);
}

// ---------------------------------------------------------------------------
// NT GEMM: C[m,n] = sum_{k in this split} A[m,k]*B[n,k].
// CTA 128x128x32, 8 warps of 64x32. lda = full row stride; K = split length;
// blockIdx.z selects the k-range (koff = z*K) and the output partial plane.
// EPI: 0 = plain fp32 store (partials) ; 3 = exp -> Cbh bf16 + atomic row sums.
// 3-stage cp.async pipeline.
// ---------------------------------------------------------------------------
template <int EPI, int FP16>
__global__ __launch_bounds__(256, 2)
void gemm_nt(const void* __restrict__ Agh, const void* __restrict__ Bgh,
             float* __restrict__ Cf, __nv_bfloat16* __restrict__ Cbh,
             float* __restrict__ sums, int N, int K, int lda)
{
    constexpr int OFF_AH = 0;
    constexpr int OFF_BH = TPB;
    constexpr int BUF    = 2 * TPB;

    extern __shared__ char smem[];
    const uint32_t sb = smem_u32(smem);

    const int tid  = threadIdx.x;
    const int wid  = tid >> 5;
    const int lane = tid & 31;
    const int g    = lane >> 2;
    const int tig  = lane & 3;
    const int wm   = wid & 1;
    const int wn   = wid >> 1;
    const int bm0  = blockIdx.y * 128;
    const int bn0  = blockIdx.x * 128;
    const int koff = blockIdx.z * K;

    if (blockIdx.z)  // partial plane 1
        Cf += (size_t)(gridDim.y * 128) * N;

    const int lrow = lane & 7;
    const int lb3  = (lane >> 3) & 1;
    const int lb4  = lane >> 4;
    const uint32_t a_lane = (uint32_t)(((wm * 64 + lb3 * 8 + lrow) * SA + lb4 * 8) * 2);
    const uint32_t b_lane = (uint32_t)(((wn * 32 + lb4 * 8 + lrow) * SA + lb3 * 8) * 2);

    float acc[4][4][4];
#pragma unroll
    for (int mi = 0; mi < 4; mi++)
#pragma unroll
        for (int ni = 0; ni < 4; ni++)
#pragma unroll
            for (int j = 0; j < 4; j++) acc[mi][ni][j] = 0.f;

    const int NC = (K + 31) >> 5;

    auto load_chunk = [&](int stage, int kt) {
        const uint32_t sbuf = sb + (uint32_t)(stage * BUF);
#pragma unroll
        for (int i = 0; i < 2; i++) {
            const int e   = tid + i * 256;
            const int row = e >> 2;
            const int kc  = (e & 3) << 3;
            const int gk  = kt + kc;
            const bool kok = gk < K;
            const uint32_t d = (uint32_t)(row * (SA * 2) + kc * 2);
            const size_t aoff = (size_t)(bm0 + row) * lda + koff + gk;
            cpa16(sbuf + OFF_AH + d, (const uint16_t*)Agh + aoff, kok);
            const bool nok = ((bn0 + row) < N) && kok;
            const size_t boff = (size_t)(bn0 + row) * lda + koff + gk;
            cpa16(sbuf + OFF_BH + d, (const uint16_t*)Bgh + boff, nok);
        }
        cpa_commit();
    };

    load_chunk(0, 0);
    load_chunk(1, 32);

    int stage = 0;
    for (int c = 0; c < NC; c++) {
        if (c + 1 < NC) cpa_wait<1>(); else cpa_wait<0>();
        __syncthreads();

        if (c + 2 < NC) {
            int ns = stage + 2; if (ns >= 3) ns -= 3;
            load_chunk(ns, (c + 2) << 5);
        }

        const uint32_t bufb = sb + (uint32_t)(stage * BUF);
#pragma unroll
        for (int ks = 0; ks < 2; ks++) {
            const uint32_t ko = (uint32_t)(ks * 32);
            uint32_t ah[4][4], bh[4][2];
#pragma unroll
            for (int mi = 0; mi < 4; mi++)
                ldm_x4(ah[mi][0], ah[mi][1], ah[mi][2], ah[mi][3],
                       bufb + OFF_AH + a_lane + (uint32_t)(mi * 16 * SA * 2) + ko);
#pragma unroll
            for (int pp = 0; pp < 2; pp++)
                ldm_x4(bh[2 * pp][0], bh[2 * pp][1], bh[2 * pp + 1][0], bh[2 * pp + 1][1],
                       bufb + OFF_BH + b_lane + (uint32_t)(pp * 16 * SA * 2) + ko);

#pragma unroll
            for (int mi = 0; mi < 4; mi++)
#pragma unroll
                for (int ni = 0; ni < 4; ni++)
                    mma_16<FP16>(acc[mi][ni], ah[mi], bh[ni]);
        }
        if (++stage == 3) stage = 0;
    }

    // ---- epilogue ----
#pragma unroll
    for (int mi = 0; mi < 4; mi++) {
        const int gm = bm0 + wm * 64 + mi * 16 + g;
        float rs01 = 0.f, rs23 = 0.f;
#pragma unroll
        for (int ni = 0; ni < 4; ni++) {
            const int gn = bn0 + wn * 32 + ni * 8 + tig * 2;
            float* cc = acc[mi][ni];
            if (EPI == 3) {
                if (gn < N) {
                    const float e0 = __expf(cc[0]), e1 = __expf(cc[1]);
                    const float e2 = __expf(cc[2]), e3 = __expf(cc[3]);
                    rs01 += e0 + e1;
                    rs23 += e2 + e3;
                    *(uint32_t*)(Cbh + (size_t)gm * N + gn)       = packbf(e0, e1);
                    *(uint32_t*)(Cbh + (size_t)(gm + 8) * N + gn) = packbf(e2, e3);
                }
            } else {
                if (gn < N) {
                    *(float2*)(Cf + (size_t)gm * N + gn)       = make_float2(cc[0], cc[1]);
                    *(float2*)(Cf + (size_t)(gm + 8) * N + gn) = make_float2(cc[2], cc[3]);
                }
            }
        }
        if (EPI == 3) {
            rs01 += __shfl_xor_sync(0xffffffffu, rs01, 1);
            rs01 += __shfl_xor_sync(0xffffffffu, rs01, 2);
            rs23 += __shfl_xor_sync(0xffffffffu, rs23, 1);
            rs23 += __shfl_xor_sync(0xffffffffu, rs23, 2);
            if (tig == 0) {
                atomicAdd(&sums[gm],     rs01);
                atomicAdd(&sums[gm + 8], rs23);
            }
        }
    }
}

// ---------------------------------------------------------------------------
// combine_q: q = tanh(p0 + p1) -> out fp32 + qh bf16.  n4 = M*D/4.
// ---------------------------------------------------------------------------
__global__ __launch_bounds__(256)
void combine_q(const float* __restrict__ p, float* __restrict__ out,
               __nv_bfloat16* __restrict__ qh, int n4)
{
    const int i = blockIdx.x * 256 + threadIdx.x;
    if (i < n4) {
        const size_t o = 4 * (size_t)i;
        float4 a = *(const float4*)(p + o);
        float4 b = *(const float4*)(p + (size_t)Mdim * Ddim + o);
        float4 v;
        v.x = tanhf(a.x + b.x); v.y = tanhf(a.y + b.y);
        v.z = tanhf(a.z + b.z); v.w = tanhf(a.w + b.w);
        *(float4*)(out + o) = v;
        *(uint2*)(qh + o) = make_uint2(packbf(v.x, v.y), packbf(v.z, v.w));
    }
}

// ---------------------------------------------------------------------------
// combine_o: out = (p0 + p1) * (1/sums[m]) + out(q).  n4 = M*D/4.
// ---------------------------------------------------------------------------
__global__ __launch_bounds__(256)
void combine_o(const float* __restrict__ p, const float* __restrict__ sums,
               float* __restrict__ out, int n4)
{
    const int i = blockIdx.x * 256 + threadIdx.x;
    if (i < n4) {
        const size_t o = 4 * (size_t)i;
        const int m = (int)(o / Ddim);
        const float s = 1.0f / sums[m];
        float4 a = *(const float4*)(p + o);
        float4 b = *(const float4*)(p + (size_t)Mdim * Ddim + o);
        float4 r = *(const float4*)(out + o);
        r.x += (a.x + b.x) * s; r.y += (a.y + b.y) * s;
        r.z += (a.z + b.z) * s; r.w += (a.w + b.w) * s;
        *(float4*)(out + o) = r;
    }
}

// ---------------------------------------------------------------------------
__global__ __launch_bounds__(256)
void conv_f16(const float* __restrict__ in, __half* __restrict__ h, int n4)
{
    const int i = blockIdx.x * 256 + threadIdx.x;
    if (i < n4) {
        const float4 v = *(const float4*)(in + 4 * (size_t)i);
        __half hh[4] = { __float2half_rn(v.x), __float2half_rn(v.y),
                         __float2half_rn(v.z), __float2half_rn(v.w) };
        *(uint2*)(h + 4 * (size_t)i) = *(const uint2*)hh;
    }
}

// E prep: Eh = bf16(E) [V,D]; Eth = bf16(E^T) [D,V]. Block (32,8).
__global__ __launch_bounds__(256)
void prep_E(const float* __restrict__ E,
            __nv_bfloat16* __restrict__ Eh, __nv_bfloat16* __restrict__ Eth,
            int V, int D)
{
    __shared__ float tile[32][33];
    const int d0 = blockIdx.x * 32;
    const int v0 = blockIdx.y * 32;
    const int tx = threadIdx.x, ty = threadIdx.y;

#pragma unroll
    for (int j = 0; j < 4; j++) {
        const int v = v0 + ty + 8 * j;
        const int d = d0 + tx;
        float val = 0.f;
        if (v < V) val = E[(size_t)v * D + d];
        tile[ty + 8 * j][tx] = val;
        if (v < V) Eh[(size_t)v * D + d] = __float2bfloat16_rn(val);
    }
    __syncthreads();
#pragma unroll
    for (int j = 0; j < 4; j++) {
        const int d = d0 + ty + 8 * j;
        const int v = v0 + tx;
        if (v < V)
            Eth[(size_t)d * V + v] = __float2bfloat16_rn(tile[tx][ty + 8 * j]);
    }
}

// ---------------------------------------------------------------------------
extern "C" void kernel_launch(void* const* d_in, const int* in_sizes, int n_in,
                              void* d_out, int out_size)
{
    (void)in_sizes; (void)n_in; (void)out_size;
    const float* x  = (const float*)d_in[0];   // [4096, 4000]
    const float* Wp = (const float*)d_in[1];   // [512, 4000]
    const float* E  = (const float*)d_in[2];   // [10000, 512]
    float* out = (float*)d_out;                // [4096, 512]

    __half *xh, *Wh;
    __nv_bfloat16 *qh, *Eh, *Eth, *Sb;
    float *sums, *part;
    cudaGetSymbolAddress((void**)&xh,   g_xh);
    cudaGetSymbolAddress((void**)&Wh,   g_Wh);
    cudaGetSymbolAddress((void**)&qh,   g_qh);
    cudaGetSymbolAddress((void**)&Eh,   g_Eh);
    cudaGetSymbolAddress((void**)&Eth,  g_Eth);
    cudaGetSymbolAddress((void**)&Sb,   g_Sb);
    cudaGetSymbolAddress((void**)&sums, g_sums);
    cudaGetSymbolAddress((void**)&part, g_part);

    constexpr int SM_G = 3 * 2 * TPB;   // 61440
    cudaFuncSetAttribute((const void*)gemm_nt<0, 1>,
                         cudaFuncAttributeMaxDynamicSharedMemorySize, SM_G);
    cudaFuncSetAttribute((const void*)gemm_nt<3, 0>,
                         cudaFuncAttributeMaxDynamicSharedMemorySize, SM_G);
    cudaFuncSetAttribute((const void*)gemm_nt<0, 0>,
                         cudaFuncAttributeMaxDynamicSharedMemorySize, SM_G);

    cudaMemsetAsync(sums, 0, Mdim * sizeof(float));

    // prep
    conv_f16<<<(Mdim * Cdim / 4 + 255) / 256, 256>>>(x, xh, Mdim * Cdim / 4);
    conv_f16<<<(Ddim * Cdim / 4 + 255) / 256, 256>>>(Wp, Wh, Ddim * Cdim / 4);
    prep_E<<<dim3(Ddim / 32, (Vdim + 31) / 32), dim3(32, 8)>>>(E, Eh, Eth, Vdim, Ddim);

    const int n4q = Mdim * Ddim / 4;

    // K1: p = x @ W^T, split-K 2 (K=2000 each), fp16
    gemm_nt<0, 1><<<dim3(Ddim / 128, Mdim / 128, 2), 256, SM_G>>>(
        xh, Wh, part, nullptr, nullptr, Ddim, Cdim / 2, Cdim);
    combine_q<<<(n4q + 255) / 256, 256>>>(part, out, qh, n4q);

    // K2: Sb = bf16(exp(qh @ Eh^T)), sums = rowsum  [N=10000, K=512]
    gemm_nt<3, 0><<<dim3((Vdim + 127) / 128, Mdim / 128, 1), 256, SM_G>>>(
        qh, Eh, nullptr, Sb, sums, Vdim, Ddim, Ddim);

    // K4: p = Sb @ Eth^T, split-K 2 (K=5000 each), bf16
    gemm_nt<0, 0><<<dim3(Ddim / 128, Mdim / 128, 2), 256, SM_G>>>(
        Sb, Eth, part, nullptr, nullptr, Ddim, Vdim / 2, Vdim);
    combine_o<<<(n4q + 255) / 256, 256>>>(part, sums, out, n4q);
}

// round 13
// speedup vs baseline: 1.5283x; 1.1584x over previous
#include <cuda_runtime.h>
#include <cuda_bf16.h>
#include <cuda_fp16.h>
#include <math.h>
#include <stdint.h>

// ============================================================================
// SDEembedding on GB300 — HMMA NT pipeline, 3-stage cp.async, split-K,
// 64x64 warp tiles (4 warps / 128 threads per CTA) for 4:1 MMA:LDSM ratio.
//   prep:  x -> xh (fp16) ; W -> Wh (fp16) ; E -> Eh, E^T -> Eth (bf16)
//   K1: p = x @ W^T (split-K 2, fp32 partials) ; combine_q: q=tanh(p0+p1)
//   K2: Sb = bf16(exp(qh @ Eh^T)), sums += rowsum
//   K4: p = Sb @ Eth^T (split-K 2) ; combine_o: out=(p0+p1)/sums + q
// ============================================================================

static constexpr int Mdim = 4096, Ddim = 512, Cdim = 4000, Vdim = 10000;

__device__ __align__(16) __half        g_xh[(size_t)Mdim * Cdim];
__device__ __align__(16) __half        g_Wh[(size_t)Ddim * Cdim];
__device__ __align__(16) __nv_bfloat16 g_qh[(size_t)Mdim * Ddim];
__device__ __align__(16) __nv_bfloat16 g_Eh[(size_t)Vdim * Ddim];
__device__ __align__(16) __nv_bfloat16 g_Eth[(size_t)Ddim * Vdim];
__device__ __align__(16) __nv_bfloat16 g_Sb[(size_t)Mdim * Vdim];
__device__ __align__(16) float g_part[2ull * Mdim * Ddim];   // split-K partials
__device__ float g_sums[Mdim];

#define SA 40   // smem row stride (16-bit elems) = 80 B: conflict-free ldmatrix
static constexpr int TPB = 10240;     // one 128x32 16-bit plane (padded)

__device__ __forceinline__ uint32_t smem_u32(const void* p) {
    uint32_t a;
    asm("{ .reg .u64 t; cvta.to.shared.u64 t, %1; cvt.u32.u64 %0, t; }"
        : "=r"(a) : "l"(p));
    return a;
}
__device__ __forceinline__ void cpa16(uint32_t dst, const void* src, bool pred) {
    int sz = pred ? 16 : 0;
    asm volatile("cp.async.cg.shared.global [%0], [%1], 16, %2;"
                 :: "r"(dst), "l"(src), "r"(sz) : "memory");
}
template <int Ng>
__device__ __forceinline__ void cpa_wait() {
    asm volatile("cp.async.wait_group %0;" :: "n"(Ng) : "memory");
}
__device__ __forceinline__ void cpa_commit() {
    asm volatile("cp.async.commit_group;" ::: "memory");
}
template <int FP16>
__device__ __forceinline__ void mma_16(float* c, const uint32_t* a, const uint32_t* b) {
    if (FP16)
        asm("mma.sync.aligned.m16n8k16.row.col.f32.f16.f16.f32 "
            "{%0,%1,%2,%3},{%4,%5,%6,%7},{%8,%9},{%0,%1,%2,%3};"
            : "+f"(c[0]), "+f"(c[1]), "+f"(c[2]), "+f"(c[3])
            : "r"(a[0]), "r"(a[1]), "r"(a[2]), "r"(a[3]), "r"(b[0]), "r"(b[1]));
    else
        asm("mma.sync.aligned.m16n8k16.row.col.f32.bf16.bf16.f32 "
            "{%0,%1,%2,%3},{%4,%5,%6,%7},{%8,%9},{%0,%1,%2,%3};"
            : "+f"(c[0]), "+f"(c[1]), "+f"(c[2]), "+f"(c[3])
            : "r"(a[0]), "r"(a[1]), "r"(a[2]), "r"(a[3]), "r"(b[0]), "r"(b[1]));
}
__device__ __forceinline__ void ldm_x4(uint32_t& r0, uint32_t& r1,
                                       uint32_t& r2, uint32_t& r3, uint32_t addr) {
    asm volatile("ldmatrix.sync.aligned.m8n8.x4.shared.b16 {%0,%1,%2,%3}, [%4];"
                 : "=r"(r0), "=r"(r1), "=r"(r2), "=r"(r3) : "r"(addr));
}
__device__ __forceinline__ uint32_t packbf(float a, float b) {
    return (uint32_t)__bfloat16_as_ushort(__float2bfloat16_rn(a)) |
           ((uint32_t)__bfloat16_as_ushort(__float2bfloat16_rn(b)) << 16);
}

// ---------------------------------------------------------------------------
// NT GEMM: C[m,n] = sum_{k in split} A[m,k]*B[n,k].
// CTA 128x128x32, 4 warps (2m x 2n), warp tile 64x64.
// lda = full row stride; K = split length; blockIdx.z -> k-range + partial plane.
// EPI: 0 = fp32 partial store ; 3 = exp -> Cbh bf16 + atomic row sums.
// 3-stage cp.async pipeline.
// ---------------------------------------------------------------------------
template <int EPI, int FP16>
__global__ __launch_bounds__(128, 2)
void gemm_nt(const void* __restrict__ Agh, const void* __restrict__ Bgh,
             float* __restrict__ Cf, __nv_bfloat16* __restrict__ Cbh,
             float* __restrict__ sums, int N, int K, int lda)
{
    constexpr int OFF_AH = 0;
    constexpr int OFF_BH = TPB;
    constexpr int BUF    = 2 * TPB;

    extern __shared__ char smem[];
    const uint32_t sb = smem_u32(smem);

    const int tid  = threadIdx.x;
    const int wid  = tid >> 5;
    const int lane = tid & 31;
    const int g    = lane >> 2;
    const int tig  = lane & 3;
    const int wm   = wid & 1;      // 2 m-groups of 64
    const int wn   = wid >> 1;     // 2 n-groups of 64
    const int bm0  = blockIdx.y * 128;
    const int bn0  = blockIdx.x * 128;
    const int koff = blockIdx.z * K;

    if (blockIdx.z)  // partial plane 1
        Cf += (size_t)(gridDim.y * 128) * N;

    const int lrow = lane & 7;
    const int lb3  = (lane >> 3) & 1;
    const int lb4  = lane >> 4;
    const uint32_t a_lane = (uint32_t)(((wm * 64 + lb3 * 8 + lrow) * SA + lb4 * 8) * 2);
    const uint32_t b_lane = (uint32_t)(((wn * 64 + lb4 * 8 + lrow) * SA + lb3 * 8) * 2);

    float acc[4][8][4];
#pragma unroll
    for (int mi = 0; mi < 4; mi++)
#pragma unroll
        for (int ni = 0; ni < 8; ni++)
#pragma unroll
            for (int j = 0; j < 4; j++) acc[mi][ni][j] = 0.f;

    const int NC = (K + 31) >> 5;

    auto load_chunk = [&](int stage, int kt) {
        const uint32_t sbuf = sb + (uint32_t)(stage * BUF);
#pragma unroll
        for (int i = 0; i < 4; i++) {
            const int e   = tid + i * 128;
            const int row = e >> 2;
            const int kc  = (e & 3) << 3;
            const int gk  = kt + kc;
            const bool kok = gk < K;
            const uint32_t d = (uint32_t)(row * (SA * 2) + kc * 2);
            const size_t aoff = (size_t)(bm0 + row) * lda + koff + gk;
            cpa16(sbuf + OFF_AH + d, (const uint16_t*)Agh + aoff, kok);
            const bool nok = ((bn0 + row) < N) && kok;
            const size_t boff = (size_t)(bn0 + row) * lda + koff + gk;
            cpa16(sbuf + OFF_BH + d, (const uint16_t*)Bgh + boff, nok);
        }
        cpa_commit();
    };

    load_chunk(0, 0);
    load_chunk(1, 32);

    int stage = 0;
    for (int c = 0; c < NC; c++) {
        if (c + 1 < NC) cpa_wait<1>(); else cpa_wait<0>();
        __syncthreads();

        if (c + 2 < NC) {
            int ns = stage + 2; if (ns >= 3) ns -= 3;
            load_chunk(ns, (c + 2) << 5);
        }

        const uint32_t bufb = sb + (uint32_t)(stage * BUF);
#pragma unroll
        for (int ks = 0; ks < 2; ks++) {
            const uint32_t ko = (uint32_t)(ks * 32);
            uint32_t ah[4][4], bh[8][2];
#pragma unroll
            for (int mi = 0; mi < 4; mi++)
                ldm_x4(ah[mi][0], ah[mi][1], ah[mi][2], ah[mi][3],
                       bufb + OFF_AH + a_lane + (uint32_t)(mi * 16 * SA * 2) + ko);
#pragma unroll
            for (int pp = 0; pp < 4; pp++)
                ldm_x4(bh[2 * pp][0], bh[2 * pp][1], bh[2 * pp + 1][0], bh[2 * pp + 1][1],
                       bufb + OFF_BH + b_lane + (uint32_t)(pp * 16 * SA * 2) + ko);

#pragma unroll
            for (int mi = 0; mi < 4; mi++)
#pragma unroll
                for (int ni = 0; ni < 8; ni++)
                    mma_16<FP16>(acc[mi][ni], ah[mi], bh[ni]);
        }
        if (++stage == 3) stage = 0;
    }

    // ---- epilogue ----
#pragma unroll
    for (int mi = 0; mi < 4; mi++) {
        const int gm = bm0 + wm * 64 + mi * 16 + g;
        float rs01 = 0.f, rs23 = 0.f;
#pragma unroll
        for (int ni = 0; ni < 8; ni++) {
            const int gn = bn0 + wn * 64 + ni * 8 + tig * 2;
            float* cc = acc[mi][ni];
            if (EPI == 3) {
                if (gn < N) {
                    const float e0 = __expf(cc[0]), e1 = __expf(cc[1]);
                    const float e2 = __expf(cc[2]), e3 = __expf(cc[3]);
                    rs01 += e0 + e1;
                    rs23 += e2 + e3;
                    *(uint32_t*)(Cbh + (size_t)gm * N + gn)       = packbf(e0, e1);
                    *(uint32_t*)(Cbh + (size_t)(gm + 8) * N + gn) = packbf(e2, e3);
                }
            } else {
                if (gn < N) {
                    *(float2*)(Cf + (size_t)gm * N + gn)       = make_float2(cc[0], cc[1]);
                    *(float2*)(Cf + (size_t)(gm + 8) * N + gn) = make_float2(cc[2], cc[3]);
                }
            }
        }
        if (EPI == 3) {
            rs01 += __shfl_xor_sync(0xffffffffu, rs01, 1);
            rs01 += __shfl_xor_sync(0xffffffffu, rs01, 2);
            rs23 += __shfl_xor_sync(0xffffffffu, rs23, 1);
            rs23 += __shfl_xor_sync(0xffffffffu, rs23, 2);
            if (tig == 0) {
                atomicAdd(&sums[gm],     rs01);
                atomicAdd(&sums[gm + 8], rs23);
            }
        }
    }
}

// ---------------------------------------------------------------------------
// combine_q: q = tanh(p0 + p1) -> out fp32 + qh bf16.  n4 = M*D/4.
// ---------------------------------------------------------------------------
__global__ __launch_bounds__(256)
void combine_q(const float* __restrict__ p, float* __restrict__ out,
               __nv_bfloat16* __restrict__ qh, int n4)
{
    const int i = blockIdx.x * 256 + threadIdx.x;
    if (i < n4) {
        const size_t o = 4 * (size_t)i;
        float4 a = *(const float4*)(p + o);
        float4 b = *(const float4*)(p + (size_t)Mdim * Ddim + o);
        float4 v;
        v.x = tanhf(a.x + b.x); v.y = tanhf(a.y + b.y);
        v.z = tanhf(a.z + b.z); v.w = tanhf(a.w + b.w);
        *(float4*)(out + o) = v;
        *(uint2*)(qh + o) = make_uint2(packbf(v.x, v.y), packbf(v.z, v.w));
    }
}

// ---------------------------------------------------------------------------
// combine_o: out = (p0 + p1) * (1/sums[m]) + out(q).  n4 = M*D/4.
// ---------------------------------------------------------------------------
__global__ __launch_bounds__(256)
void combine_o(const float* __restrict__ p, const float* __restrict__ sums,
               float* __restrict__ out, int n4)
{
    const int i = blockIdx.x * 256 + threadIdx.x;
    if (i < n4) {
        const size_t o = 4 * (size_t)i;
        const int m = (int)(o / Ddim);
        const float s = 1.0f / sums[m];
        float4 a = *(const float4*)(p + o);
        float4 b = *(const float4*)(p + (size_t)Mdim * Ddim + o);
        float4 r = *(const float4*)(out + o);
        r.x += (a.x + b.x) * s; r.y += (a.y + b.y) * s;
        r.z += (a.z + b.z) * s; r.w += (a.w + b.w) * s;
        *(float4*)(out + o) = r;
    }
}

// ---------------------------------------------------------------------------
__global__ __launch_bounds__(256)
void conv_f16(const float* __restrict__ in, __half* __restrict__ h, int n4)
{
    const int i = blockIdx.x * 256 + threadIdx.x;
    if (i < n4) {
        const float4 v = *(const float4*)(in + 4 * (size_t)i);
        __half hh[4] = { __float2half_rn(v.x), __float2half_rn(v.y),
                         __float2half_rn(v.z), __float2half_rn(v.w) };
        *(uint2*)(h + 4 * (size_t)i) = *(const uint2*)hh;
    }
}

// E prep: Eh = bf16(E) [V,D]; Eth = bf16(E^T) [D,V]. Block (32,8).
__global__ __launch_bounds__(256)
void prep_E(const float* __restrict__ E,
            __nv_bfloat16* __restrict__ Eh, __nv_bfloat16* __restrict__ Eth,
            int V, int D)
{
    __shared__ float tile[32][33];
    const int d0 = blockIdx.x * 32;
    const int v0 = blockIdx.y * 32;
    const int tx = threadIdx.x, ty = threadIdx.y;

#pragma unroll
    for (int j = 0; j < 4; j++) {
        const int v = v0 + ty + 8 * j;
        const int d = d0 + tx;
        float val = 0.f;
        if (v < V) val = E[(size_t)v * D + d];
        tile[ty + 8 * j][tx] = val;
        if (v < V) Eh[(size_t)v * D + d] = __float2bfloat16_rn(val);
    }
    __syncthreads();
#pragma unroll
    for (int j = 0; j < 4; j++) {
        const int d = d0 + ty + 8 * j;
        const int v = v0 + tx;
        if (v < V)
            Eth[(size_t)d * V + v] = __float2bfloat16_rn(tile[tx][ty + 8 * j]);
    }
}

// ---------------------------------------------------------------------------
extern "C" void kernel_launch(void* const* d_in, const int* in_sizes, int n_in,
                              void* d_out, int out_size)
{
    (void)in_sizes; (void)n_in; (void)out_size;
    const float* x  = (const float*)d_in[0];   // [4096, 4000]
    const float* Wp = (const float*)d_in[1];   // [512, 4000]
    const float* E  = (const float*)d_in[2];   // [10000, 512]
    float* out = (float*)d_out;                // [4096, 512]

    __half *xh, *Wh;
    __nv_bfloat16 *qh, *Eh, *Eth, *Sb;
    float *sums, *part;
    cudaGetSymbolAddress((void**)&xh,   g_xh);
    cudaGetSymbolAddress((void**)&Wh,   g_Wh);
    cudaGetSymbolAddress((void**)&qh,   g_qh);
    cudaGetSymbolAddress((void**)&Eh,   g_Eh);
    cudaGetSymbolAddress((void**)&Eth,  g_Eth);
    cudaGetSymbolAddress((void**)&Sb,   g_Sb);
    cudaGetSymbolAddress((void**)&sums, g_sums);
    cudaGetSymbolAddress((void**)&part, g_part);

    constexpr int SM_G = 3 * 2 * TPB;   // 61440
    cudaFuncSetAttribute((const void*)gemm_nt<0, 1>,
                         cudaFuncAttributeMaxDynamicSharedMemorySize, SM_G);
    cudaFuncSetAttribute((const void*)gemm_nt<3, 0>,
                         cudaFuncAttributeMaxDynamicSharedMemorySize, SM_G);
    cudaFuncSetAttribute((const void*)gemm_nt<0, 0>,
                         cudaFuncAttributeMaxDynamicSharedMemorySize, SM_G);

    cudaMemsetAsync(sums, 0, Mdim * sizeof(float));

    // prep
    conv_f16<<<(Mdim * Cdim / 4 + 255) / 256, 256>>>(x, xh, Mdim * Cdim / 4);
    conv_f16<<<(Ddim * Cdim / 4 + 255) / 256, 256>>>(Wp, Wh, Ddim * Cdim / 4);
    prep_E<<<dim3(Ddim / 32, (Vdim + 31) / 32), dim3(32, 8)>>>(E, Eh, Eth, Vdim, Ddim);

    const int n4q = Mdim * Ddim / 4;

    // K1: p = x @ W^T, split-K 2 (K=2000 each), fp16
    gemm_nt<0, 1><<<dim3(Ddim / 128, Mdim / 128, 2), 128, SM_G>>>(
        xh, Wh, part, nullptr, nullptr, Ddim, Cdim / 2, Cdim);
    combine_q<<<(n4q + 255) / 256, 256>>>(part, out, qh, n4q);

    // K2: Sb = bf16(exp(qh @ Eh^T)), sums = rowsum  [N=10000, K=512]
    gemm_nt<3, 0><<<dim3((Vdim + 127) / 128, Mdim / 128, 1), 128, SM_G>>>(
        qh, Eh, nullptr, Sb, sums, Vdim, Ddim, Ddim);

    // K4: p = Sb @ Eth^T, split-K 2 (K=5000 each), bf16
    gemm_nt<0, 0><<<dim3(Ddim / 128, Mdim / 128, 2), 128, SM_G>>>(
        Sb, Eth, part, nullptr, nullptr, Ddim, Vdim / 2, Vdim);
    combine_o<<<(n4q + 255) / 256, 256>>>(part, sums, out, n4q);
}